// round 2
// baseline (speedup 1.0000x reference)
#include <cuda_runtime.h>

static constexpr int B  = 2;
static constexpr int S  = 2048;
static constexpr int D  = 1024;
static constexpr int NH = 16;
static constexpr int DK = 64;
static constexpr int M  = B * S;   // 4096

// Scratch (allocation-free rule: __device__ globals)
__device__ float g_Q [M * D];
__device__ float g_K [M * D];
__device__ float g_V [M * D];
__device__ float g_AT[M * D];

// ---------------------------------------------------------------------------
// GEMM body: C[m][n] = sum_k A[m][k] * W[n][k]   (A:[4096,1024], W:[1024,1024])
// 64x64 block tile, BK=32, 256 threads, 4x4 micro-tile. Optional fused RoPE.
// ---------------------------------------------------------------------------
__device__ __forceinline__ void gemm_body(const float* __restrict__ A,
                                          const float* __restrict__ W,
                                          float* __restrict__ C,
                                          const int* __restrict__ pos,
                                          bool doRope)
{
    __shared__ __align__(16) float As[64 * 33];
    __shared__ __align__(16) float Bs[64 * 33];
    const int t  = threadIdx.x;
    const int tx = t & 15;
    const int ty = t >> 4;
    const int mBase = blockIdx.y * 64;
    const int nBase = blockIdx.x * 64;

    float acc[4][4] = {};

    for (int kt = 0; kt < D; kt += 32) {
#pragma unroll
        for (int j = 0; j < 2; j++) {
            int e4  = t + j * 256;
            int row = e4 >> 3;
            int kq  = (e4 & 7) * 4;
            float4 av = *(const float4*)&A[(size_t)(mBase + row) * D + kt + kq];
            float4 bv = *(const float4*)&W[(size_t)(nBase + row) * D + kt + kq];
            As[row * 33 + kq + 0] = av.x;
            As[row * 33 + kq + 1] = av.y;
            As[row * 33 + kq + 2] = av.z;
            As[row * 33 + kq + 3] = av.w;
            Bs[row * 33 + kq + 0] = bv.x;
            Bs[row * 33 + kq + 1] = bv.y;
            Bs[row * 33 + kq + 2] = bv.z;
            Bs[row * 33 + kq + 3] = bv.w;
        }
        __syncthreads();
#pragma unroll 8
        for (int kk = 0; kk < 32; kk++) {
            float a[4], b[4];
#pragma unroll
            for (int i = 0; i < 4; i++) a[i] = As[(ty * 4 + i) * 33 + kk];
#pragma unroll
            for (int j = 0; j < 4; j++) b[j] = Bs[(tx * 4 + j) * 33 + kk];
#pragma unroll
            for (int i = 0; i < 4; i++)
#pragma unroll
                for (int j = 0; j < 4; j++)
                    acc[i][j] += a[i] * b[j];
        }
        __syncthreads();
    }

#pragma unroll
    for (int i = 0; i < 4; i++) {
        int m = mBase + ty * 4 + i;
        float o0 = acc[i][0], o1 = acc[i][1], o2 = acc[i][2], o3 = acc[i][3];
        if (doRope) {
            // Column tile (64 wide) == exactly one head. In-head even index j2
            // for pair p is tx*4 + 2p; freq = theta^(-j2/64).
            int p = pos[m & (S - 1)];
            int colBase = tx * 4;
            {
                float freq = powf(10000.0f, -(float)colBase * (1.0f / 64.0f));
                float ang  = (float)p * freq;
                float sn, cs; sincosf(ang, &sn, &cs);
                float v0 = o0, v1 = o1;
                o0 = cs * v0 - sn * v1;
                o1 = sn * v0 + cs * v1;
            }
            {
                float freq = powf(10000.0f, -(float)(colBase + 2) * (1.0f / 64.0f));
                float ang  = (float)p * freq;
                float sn, cs; sincosf(ang, &sn, &cs);
                float v0 = o2, v1 = o3;
                o2 = cs * v0 - sn * v1;
                o3 = sn * v0 + cs * v1;
            }
        }
        *(float4*)&C[(size_t)m * D + nBase + tx * 4] = make_float4(o0, o1, o2, o3);
    }
}

__global__ void __launch_bounds__(256)
qkv_kernel(const float* __restrict__ x,
           const float* __restrict__ WQ,
           const float* __restrict__ WK,
           const float* __restrict__ WV,
           const int* __restrict__ pos)
{
    int z = blockIdx.z;
    const float* W = (z == 0) ? WQ : (z == 1) ? WK : WV;
    float* Cd      = (z == 0) ? g_Q : (z == 1) ? g_K : g_V;
    gemm_body(x, W, Cd, pos, z < 2);
}

__global__ void __launch_bounds__(256)
oproj_kernel(const float* __restrict__ WO, float* __restrict__ out)
{
    gemm_body(g_AT, WO, out, nullptr, false);
}

// ---------------------------------------------------------------------------
// Flash attention: one block per (b, h, 64-row q tile). 256 threads = 8 warps,
// each warp owns 8 q rows; each lane owns score/output columns {lane, lane+32}.
// Online softmax; causal: only qtile+1 KV tiles.
// smem: Qs[64][64] | Kt[64][65] (d-major) | Vs[64][65] | Ps[8][8][64]
// ---------------------------------------------------------------------------
static constexpr int ATT_SMEM_FLOATS = 4096 + 4160 + 4160 + 4096;  // 16512
static constexpr int ATT_SMEM_BYTES  = ATT_SMEM_FLOATS * 4;        // 66048

__global__ void __launch_bounds__(256)
attn_kernel()
{
    extern __shared__ float sm[];
    float* Qs = sm;            // 64*64
    float* Kt = sm + 4096;     // 64*65, Kt[d*65 + c]
    float* Vs = Kt + 4160;     // 64*65, Vs[c*65 + d]
    float* Ps = Vs + 4160;     // 8 warps * 8 rows * 64

    const int t    = threadIdx.x;
    const int lane = t & 31;
    const int w    = t >> 5;
    const int qt   = blockIdx.x;
    const int h    = blockIdx.y;
    const int b    = blockIdx.z;

    // Load Q tile (scaled by 1/sqrt(dk) = 0.125)
    const float* Qg = g_Q + ((size_t)(b * S + qt * 64)) * D + h * DK;
#pragma unroll
    for (int j = 0; j < 4; j++) {
        int e4 = t + j * 256;
        int r  = e4 >> 4;
        int dq = (e4 & 15) * 4;
        float4 v = *(const float4*)(Qg + (size_t)r * D + dq);
        *(float4*)&Qs[r * 64 + dq] =
            make_float4(v.x * 0.125f, v.y * 0.125f, v.z * 0.125f, v.w * 0.125f);
    }

    float m_i[8], l_i[8], accv[8][2];
#pragma unroll
    for (int r = 0; r < 8; r++) {
        m_i[r] = -1e30f; l_i[r] = 0.0f; accv[r][0] = 0.0f; accv[r][1] = 0.0f;
    }

    const float* KgBase = g_K + ((size_t)(b * S)) * D + h * DK;
    const float* VgBase = g_V + ((size_t)(b * S)) * D + h * DK;
    float* Pw = Ps + w * 512;
    const float* qrow = Qs + (w * 8) * 64;

    for (int tt = 0; tt <= qt; tt++) {
        __syncthreads();   // previous iteration's PV reads of Vs done
#pragma unroll
        for (int j = 0; j < 4; j++) {
            int e4 = t + j * 256;
            int c  = e4 >> 4;
            int dq = (e4 & 15) * 4;
            float4 kv = *(const float4*)(KgBase + (size_t)(tt * 64 + c) * D + dq);
            Kt[(dq + 0) * 65 + c] = kv.x;
            Kt[(dq + 1) * 65 + c] = kv.y;
            Kt[(dq + 2) * 65 + c] = kv.z;
            Kt[(dq + 3) * 65 + c] = kv.w;
            float4 vv = *(const float4*)(VgBase + (size_t)(tt * 64 + c) * D + dq);
            Vs[c * 65 + dq + 0] = vv.x;
            Vs[c * 65 + dq + 1] = vv.y;
            Vs[c * 65 + dq + 2] = vv.z;
            Vs[c * 65 + dq + 3] = vv.w;
        }
        __syncthreads();

        // S = Q K^T  (scaled Q)
        float sc[8][2];
#pragma unroll
        for (int r = 0; r < 8; r++) { sc[r][0] = 0.0f; sc[r][1] = 0.0f; }
#pragma unroll 8
        for (int d = 0; d < 64; d++) {
            float k0 = Kt[d * 65 + lane];
            float k1 = Kt[d * 65 + 32 + lane];
#pragma unroll
            for (int r = 0; r < 8; r++) {
                float q = qrow[r * 64 + d];
                sc[r][0] += q * k0;
                sc[r][1] += q * k1;
            }
        }

        if (tt == qt) {   // diagonal tile: causal mask
#pragma unroll
            for (int r = 0; r < 8; r++) {
                int row = w * 8 + r;
                if (lane > row)      sc[r][0] = -1e30f;
                if (lane + 32 > row) sc[r][1] = -1e30f;
            }
        }

        // Online softmax update
#pragma unroll
        for (int r = 0; r < 8; r++) {
            float mx = fmaxf(sc[r][0], sc[r][1]);
#pragma unroll
            for (int off = 16; off > 0; off >>= 1)
                mx = fmaxf(mx, __shfl_xor_sync(0xffffffffu, mx, off));
            float mnew  = fmaxf(m_i[r], mx);
            float alpha = __expf(m_i[r] - mnew);
            float p0 = __expf(sc[r][0] - mnew);
            float p1 = __expf(sc[r][1] - mnew);
            float rs = p0 + p1;
#pragma unroll
            for (int off = 16; off > 0; off >>= 1)
                rs += __shfl_xor_sync(0xffffffffu, rs, off);
            l_i[r] = l_i[r] * alpha + rs;
            m_i[r] = mnew;
            accv[r][0] *= alpha;
            accv[r][1] *= alpha;
            Pw[r * 64 + lane]      = p0;
            Pw[r * 64 + 32 + lane] = p1;
        }
        __syncwarp();

        // O += P V
#pragma unroll 8
        for (int c = 0; c < 64; c++) {
            float v0 = Vs[c * 65 + lane];
            float v1 = Vs[c * 65 + 32 + lane];
#pragma unroll
            for (int r = 0; r < 8; r++) {
                float p = Pw[r * 64 + c];
                accv[r][0] += p * v0;
                accv[r][1] += p * v1;
            }
        }
        __syncwarp();
    }

    // Epilogue: normalize + store [B,S,D] layout
    float* Og = g_AT + ((size_t)(b * S + qt * 64 + w * 8)) * D + h * DK;
#pragma unroll
    for (int r = 0; r < 8; r++) {
        float inv = 1.0f / l_i[r];
        Og[(size_t)r * D + lane]      = accv[r][0] * inv;
        Og[(size_t)r * D + 32 + lane] = accv[r][1] * inv;
    }
}

// ---------------------------------------------------------------------------
extern "C" void kernel_launch(void* const* d_in, const int* in_sizes, int n_in,
                              void* d_out, int out_size)
{
    const float* x   = (const float*)d_in[0];
    const int*   pos = (const int*)  d_in[1];
    const float* WQ  = (const float*)d_in[2];
    const float* WK  = (const float*)d_in[3];
    const float* WV  = (const float*)d_in[4];
    const float* WO  = (const float*)d_in[5];
    float* out = (float*)d_out;

    qkv_kernel<<<dim3(D / 64, M / 64, 3), 256>>>(x, WQ, WK, WV, pos);

    cudaFuncSetAttribute(attn_kernel,
                         cudaFuncAttributeMaxDynamicSharedMemorySize,
                         ATT_SMEM_BYTES);
    attn_kernel<<<dim3(S / 64, NH, B), 256, ATT_SMEM_BYTES>>>();

    oproj_kernel<<<dim3(D / 64, M / 64, 1), 256>>>(WO, out);
}

// round 3
// speedup vs baseline: 1.0554x; 1.0554x over previous
#include <cuda_runtime.h>

static constexpr int B  = 2;
static constexpr int S  = 2048;
static constexpr int D  = 1024;
static constexpr int NH = 16;
static constexpr int DK = 64;
static constexpr int M  = B * S;   // 4096

// Scratch (allocation-free rule: __device__ globals)
__device__ float g_Q [M * D];
__device__ float g_K [M * D];
__device__ float g_V [M * D];
__device__ float g_AT[M * D];

// ---------------------------------------------------------------------------
// GEMM: C[m][n] = sum_k A[m][k] * W[n][k]
// 128x128 block tile, BK=16, 256 threads, 8x8 micro-tile (split 4+4 at +64).
// Optional fused RoPE on 64-wide head groups.
// ---------------------------------------------------------------------------
__device__ __forceinline__ void gemm128(const float* __restrict__ A,
                                        const float* __restrict__ W,
                                        float* __restrict__ C,
                                        const int* __restrict__ pos,
                                        bool doRope)
{
    __shared__ __align__(16) float As[16][132];   // [k][m]
    __shared__ __align__(16) float Bs[16][132];   // [k][n]

    const int t     = threadIdx.x;
    const int tx    = t & 15;
    const int ty    = t >> 4;
    const int mBase = blockIdx.y * 128;
    const int nBase = blockIdx.x * 128;

    const int lrow  = t >> 1;          // 0..127
    const int lhalf = (t & 1) * 8;     // k-offset 0 or 8

    const float* Ag = A + (size_t)(mBase + lrow) * D + lhalf;
    const float* Wg = W + (size_t)(nBase + lrow) * D + lhalf;

    float acc[8][8];
#pragma unroll
    for (int i = 0; i < 8; i++)
#pragma unroll
        for (int j = 0; j < 8; j++) acc[i][j] = 0.0f;

    for (int kt = 0; kt < D; kt += 16) {
        float4 a0 = *(const float4*)(Ag + kt);
        float4 a1 = *(const float4*)(Ag + kt + 4);
        float4 b0 = *(const float4*)(Wg + kt);
        float4 b1 = *(const float4*)(Wg + kt + 4);

        __syncthreads();   // previous tile's compute done before overwrite
        As[lhalf + 0][lrow] = a0.x;  As[lhalf + 1][lrow] = a0.y;
        As[lhalf + 2][lrow] = a0.z;  As[lhalf + 3][lrow] = a0.w;
        As[lhalf + 4][lrow] = a1.x;  As[lhalf + 5][lrow] = a1.y;
        As[lhalf + 6][lrow] = a1.z;  As[lhalf + 7][lrow] = a1.w;
        Bs[lhalf + 0][lrow] = b0.x;  Bs[lhalf + 1][lrow] = b0.y;
        Bs[lhalf + 2][lrow] = b0.z;  Bs[lhalf + 3][lrow] = b0.w;
        Bs[lhalf + 4][lrow] = b1.x;  Bs[lhalf + 5][lrow] = b1.y;
        Bs[lhalf + 6][lrow] = b1.z;  Bs[lhalf + 7][lrow] = b1.w;
        __syncthreads();

#pragma unroll
        for (int kk = 0; kk < 16; kk++) {
            float4 fa0 = *(const float4*)&As[kk][ty * 4];
            float4 fa1 = *(const float4*)&As[kk][ty * 4 + 64];
            float4 fb0 = *(const float4*)&Bs[kk][tx * 4];
            float4 fb1 = *(const float4*)&Bs[kk][tx * 4 + 64];
            float af[8] = {fa0.x, fa0.y, fa0.z, fa0.w, fa1.x, fa1.y, fa1.z, fa1.w};
            float bf[8] = {fb0.x, fb0.y, fb0.z, fb0.w, fb1.x, fb1.y, fb1.z, fb1.w};
#pragma unroll
            for (int i = 0; i < 8; i++)
#pragma unroll
                for (int j = 0; j < 8; j++)
                    acc[i][j] += af[i] * bf[j];
        }
    }

    // Epilogue (+ optional RoPE). Row group ih: rows ty*4+ih*64; col group jh.
#pragma unroll
    for (int ih = 0; ih < 2; ih++) {
#pragma unroll
        for (int i = 0; i < 4; i++) {
            int m  = mBase + ih * 64 + ty * 4 + i;
            int ia = ih * 4 + i;
            int p  = doRope ? pos[m & (S - 1)] : 0;
#pragma unroll
            for (int jh = 0; jh < 2; jh++) {
                float o0 = acc[ia][jh * 4 + 0];
                float o1 = acc[ia][jh * 4 + 1];
                float o2 = acc[ia][jh * 4 + 2];
                float o3 = acc[ia][jh * 4 + 3];
                int col = nBase + jh * 64 + tx * 4;
                if (doRope) {
                    int inHead = col & 63;   // float4 holds 2 whole rotation pairs
                    {
                        float freq = powf(10000.0f, -(float)inHead * (1.0f / 64.0f));
                        float sn, cs; sincosf((float)p * freq, &sn, &cs);
                        float v0 = o0, v1 = o1;
                        o0 = cs * v0 - sn * v1;
                        o1 = sn * v0 + cs * v1;
                    }
                    {
                        float freq = powf(10000.0f, -(float)(inHead + 2) * (1.0f / 64.0f));
                        float sn, cs; sincosf((float)p * freq, &sn, &cs);
                        float v0 = o2, v1 = o3;
                        o2 = cs * v0 - sn * v1;
                        o3 = sn * v0 + cs * v1;
                    }
                }
                *(float4*)&C[(size_t)m * D + col] = make_float4(o0, o1, o2, o3);
            }
        }
    }
}

__global__ void __launch_bounds__(256)
qkv_kernel(const float* __restrict__ x,
           const float* __restrict__ WQ,
           const float* __restrict__ WK,
           const float* __restrict__ WV,
           const int* __restrict__ pos)
{
    int z = blockIdx.z;
    const float* W = (z == 0) ? WQ : (z == 1) ? WK : WV;
    float* Cd      = (z == 0) ? g_Q : (z == 1) ? g_K : g_V;
    gemm128(x, W, Cd, pos, z < 2);
}

__global__ void __launch_bounds__(256)
oproj_kernel(const float* __restrict__ WO, float* __restrict__ out)
{
    gemm128(g_AT, WO, out, nullptr, false);
}

// ---------------------------------------------------------------------------
// Flash attention: one block per (b, h, 64-row q tile). 256 threads = 8 warps,
// each warp owns 8 q rows. QK^T: lane owns score cols {lane, lane+32},
// d-vectorized. PV: lane owns d-float4 (lane&15)*4 and 4 rows (lane>>4 half).
// smem: Qs[64][68] | Ks[64][68] | Vs[64][68] | Ps[8 warps][8][64]
// ---------------------------------------------------------------------------
static constexpr int ATT_SMEM_FLOATS = 3 * 64 * 68 + 8 * 8 * 64;   // 17152
static constexpr int ATT_SMEM_BYTES  = ATT_SMEM_FLOATS * 4;        // 68608

__global__ void __launch_bounds__(256)
attn_kernel()
{
    extern __shared__ float sm[];
    float* Qs = sm;                 // [r][d] stride 68
    float* Ks = Qs + 64 * 68;       // [c][d] stride 68
    float* Vs = Ks + 64 * 68;       // [c][d] stride 68
    float* Ps = Vs + 64 * 68;       // per warp: [r 0..7][c 0..63]

    const int t    = threadIdx.x;
    const int lane = t & 31;
    const int w    = t >> 5;
    const int qt   = blockIdx.x;
    const int h    = blockIdx.y;
    const int b    = blockIdx.z;

    // Load Q tile scaled by 1/sqrt(dk)=0.125. row=t>>2, 4 float4 per thread.
    {
        const float* Qg = g_Q + ((size_t)(b * S + qt * 64)) * D + h * DK;
        int r  = t >> 2;
        int d0 = (t & 3) * 4;
#pragma unroll
        for (int j = 0; j < 4; j++) {
            int dq = d0 + j * 16;
            float4 v = *(const float4*)(Qg + (size_t)r * D + dq);
            *(float4*)&Qs[r * 68 + dq] =
                make_float4(v.x * 0.125f, v.y * 0.125f, v.z * 0.125f, v.w * 0.125f);
        }
    }

    float m_i[8], l_i[8];
    float4 accO[4];
#pragma unroll
    for (int r = 0; r < 8; r++) { m_i[r] = -1e30f; l_i[r] = 0.0f; }
#pragma unroll
    for (int i = 0; i < 4; i++) accO[i] = make_float4(0.f, 0.f, 0.f, 0.f);

    const float* KgBase = g_K + ((size_t)(b * S)) * D + h * DK;
    const float* VgBase = g_V + ((size_t)(b * S)) * D + h * DK;
    float* Pw = Ps + w * 512;

    const int dc = (lane & 15) * 4;   // PV: d-columns owned by this lane
    const int rh = lane >> 4;         // PV: row-half owned by this lane

    for (int tt = 0; tt <= qt; tt++) {
        __syncthreads();   // previous tile's compute reads done
        {
            int r  = t >> 2;
            int d0 = (t & 3) * 4;
            const float* Kg = KgBase + (size_t)(tt * 64 + r) * D;
            const float* Vg = VgBase + (size_t)(tt * 64 + r) * D;
#pragma unroll
            for (int j = 0; j < 4; j++) {
                int dq = d0 + j * 16;
                *(float4*)&Ks[r * 68 + dq] = *(const float4*)(Kg + dq);
                *(float4*)&Vs[r * 68 + dq] = *(const float4*)(Vg + dq);
            }
        }
        __syncthreads();

        // ---- S = Q K^T (Q pre-scaled) ----
        float sc0[8], sc1[8];
#pragma unroll
        for (int r = 0; r < 8; r++) { sc0[r] = 0.0f; sc1[r] = 0.0f; }
        const float* KsA = Ks + lane * 68;
        const float* KsB = Ks + (lane + 32) * 68;
        const float* Qw  = Qs + (w * 8) * 68;
#pragma unroll
        for (int d4 = 0; d4 < 16; d4++) {
            float4 ka = *(const float4*)(KsA + d4 * 4);
            float4 kb = *(const float4*)(KsB + d4 * 4);
#pragma unroll
            for (int r = 0; r < 8; r++) {
                float4 q = *(const float4*)(Qw + r * 68 + d4 * 4);
                sc0[r] += q.x * ka.x + q.y * ka.y + q.z * ka.z + q.w * ka.w;
                sc1[r] += q.x * kb.x + q.y * kb.y + q.z * kb.z + q.w * kb.w;
            }
        }

        if (tt == qt) {   // causal mask on diagonal tile
#pragma unroll
            for (int r = 0; r < 8; r++) {
                int row = w * 8 + r;
                if (lane > row)      sc0[r] = -1e30f;
                if (lane + 32 > row) sc1[r] = -1e30f;
            }
        }

        // ---- online softmax ----
        float alpha[8];
#pragma unroll
        for (int r = 0; r < 8; r++) {
            float mx = fmaxf(sc0[r], sc1[r]);
#pragma unroll
            for (int off = 16; off > 0; off >>= 1)
                mx = fmaxf(mx, __shfl_xor_sync(0xffffffffu, mx, off));
            float mnew = fmaxf(m_i[r], mx);
            alpha[r]   = __expf(m_i[r] - mnew);
            float p0 = __expf(sc0[r] - mnew);
            float p1 = __expf(sc1[r] - mnew);
            float rs = p0 + p1;
#pragma unroll
            for (int off = 16; off > 0; off >>= 1)
                rs += __shfl_xor_sync(0xffffffffu, rs, off);
            l_i[r] = l_i[r] * alpha[r] + rs;
            m_i[r] = mnew;
            Pw[r * 64 + lane]      = p0;
            Pw[r * 64 + 32 + lane] = p1;
        }
#pragma unroll
        for (int i = 0; i < 4; i++) {
            float a = alpha[rh * 4 + i];
            accO[i].x *= a; accO[i].y *= a; accO[i].z *= a; accO[i].w *= a;
        }
        __syncwarp();

        // ---- O += P V ----
#pragma unroll
        for (int c4 = 0; c4 < 16; c4++) {
            float4 v0 = *(const float4*)&Vs[(c4 * 4 + 0) * 68 + dc];
            float4 v1 = *(const float4*)&Vs[(c4 * 4 + 1) * 68 + dc];
            float4 v2 = *(const float4*)&Vs[(c4 * 4 + 2) * 68 + dc];
            float4 v3 = *(const float4*)&Vs[(c4 * 4 + 3) * 68 + dc];
#pragma unroll
            for (int i = 0; i < 4; i++) {
                float4 p = *(const float4*)&Pw[(rh * 4 + i) * 64 + c4 * 4];
                accO[i].x += p.x * v0.x + p.y * v1.x + p.z * v2.x + p.w * v3.x;
                accO[i].y += p.x * v0.y + p.y * v1.y + p.z * v2.y + p.w * v3.y;
                accO[i].z += p.x * v0.z + p.y * v1.z + p.z * v2.z + p.w * v3.z;
                accO[i].w += p.x * v0.w + p.y * v1.w + p.z * v2.w + p.w * v3.w;
            }
        }
        __syncwarp();   // Pw reads done before next tile overwrites
    }

    // Epilogue: normalize + store. Lane writes rows w*8+rh*4+i, cols dc..dc+3.
    float* Og = g_AT + ((size_t)(b * S + qt * 64 + w * 8)) * D + h * DK;
#pragma unroll
    for (int i = 0; i < 4; i++) {
        int   rr  = rh * 4 + i;
        float inv = 1.0f / l_i[rr];
        *(float4*)(Og + (size_t)rr * D + dc) =
            make_float4(accO[i].x * inv, accO[i].y * inv,
                        accO[i].z * inv, accO[i].w * inv);
    }
}

// ---------------------------------------------------------------------------
extern "C" void kernel_launch(void* const* d_in, const int* in_sizes, int n_in,
                              void* d_out, int out_size)
{
    const float* x   = (const float*)d_in[0];
    const int*   pos = (const int*)  d_in[1];
    const float* WQ  = (const float*)d_in[2];
    const float* WK  = (const float*)d_in[3];
    const float* WV  = (const float*)d_in[4];
    const float* WO  = (const float*)d_in[5];
    float* out = (float*)d_out;

    qkv_kernel<<<dim3(D / 128, M / 128, 3), 256>>>(x, WQ, WK, WV, pos);

    cudaFuncSetAttribute(attn_kernel,
                         cudaFuncAttributeMaxDynamicSharedMemorySize,
                         ATT_SMEM_BYTES);
    attn_kernel<<<dim3(S / 64, NH, B), 256, ATT_SMEM_BYTES>>>();

    oproj_kernel<<<dim3(D / 128, M / 128, 1), 256>>>(WO, out);
}

// round 4
// speedup vs baseline: 2.6752x; 2.5347x over previous
#include <cuda_runtime.h>
#include <cstdint>

static constexpr int B  = 2;
static constexpr int S  = 2048;
static constexpr int D  = 1024;
static constexpr int NH = 16;
static constexpr int DK = 64;
static constexpr int M  = B * S;   // 4096

// Scratch (allocation-free rule: __device__ globals)
__device__ float g_Q [M * D];
__device__ float g_K [M * D];
__device__ float g_V [M * D];
__device__ float g_AT[M * D];

// ---------------------------------------------------------------------------
// tf32 helpers
// ---------------------------------------------------------------------------
__device__ __forceinline__ uint32_t f2tf(float f) {
    uint32_t o;
    asm("cvt.rna.tf32.f32 %0, %1;" : "=r"(o) : "f"(f));
    return o;
}

// D += A(16x8 row) * B(8x8 col); c/d fp32
__device__ __forceinline__ void mma8(float* c, const uint32_t* a, const uint32_t* b) {
    asm volatile(
        "mma.sync.aligned.m16n8k8.row.col.f32.tf32.tf32.f32 "
        "{%0,%1,%2,%3}, {%4,%5,%6,%7}, {%8,%9}, {%0,%1,%2,%3};"
        : "+f"(c[0]), "+f"(c[1]), "+f"(c[2]), "+f"(c[3])
        : "r"(a[0]), "r"(a[1]), "r"(a[2]), "r"(a[3]), "r"(b[0]), "r"(b[1]));
}

// ---------------------------------------------------------------------------
// GEMM: C[m][n] = sum_k A[m][k] * W[n][k]   (tf32 tensor-core)
// 128x128 block tile, BK=16, 256 threads = 8 warps in 2x4 (each 64m x 32n).
// smem stride 20 (==20 mod 32) -> fragment loads conflict-free.
// ---------------------------------------------------------------------------
static constexpr int GS = 20;

__device__ __forceinline__ void gemm_tc(const float* __restrict__ A,
                                        const float* __restrict__ W,
                                        float* __restrict__ C,
                                        const int* __restrict__ pos,
                                        bool doRope)
{
    __shared__ uint32_t As[128 * GS];
    __shared__ uint32_t Bs[128 * GS];

    const int t    = threadIdx.x;
    const int lane = t & 31;
    const int w    = t >> 5;
    const int g    = lane >> 2;     // group (row) id 0..7
    const int tq   = lane & 3;      // thread-in-group 0..3
    const int wr   = w >> 2;        // warp row 0..1 (64 m each)
    const int wc   = w & 3;         // warp col 0..3 (32 n each)
    const int mBase = blockIdx.y * 128;
    const int nBase = blockIdx.x * 128;

    float acc[4][4][4];
#pragma unroll
    for (int i = 0; i < 4; i++)
#pragma unroll
        for (int j = 0; j < 4; j++)
#pragma unroll
            for (int r = 0; r < 4; r++) acc[i][j][r] = 0.0f;

    for (int kt = 0; kt < D; kt += 16) {
        float4 av[2], bv[2];
#pragma unroll
        for (int p = 0; p < 2; p++) {
            int slot = t + p * 256;
            int row  = slot >> 2;
            int kq   = (slot & 3) * 4;
            av[p] = *(const float4*)&A[(size_t)(mBase + row) * D + kt + kq];
            bv[p] = *(const float4*)&W[(size_t)(nBase + row) * D + kt + kq];
        }
        __syncthreads();
#pragma unroll
        for (int p = 0; p < 2; p++) {
            int slot = t + p * 256;
            int row  = slot >> 2;
            int kq   = (slot & 3) * 4;
            As[row * GS + kq + 0] = f2tf(av[p].x);
            As[row * GS + kq + 1] = f2tf(av[p].y);
            As[row * GS + kq + 2] = f2tf(av[p].z);
            As[row * GS + kq + 3] = f2tf(av[p].w);
            Bs[row * GS + kq + 0] = f2tf(bv[p].x);
            Bs[row * GS + kq + 1] = f2tf(bv[p].y);
            Bs[row * GS + kq + 2] = f2tf(bv[p].z);
            Bs[row * GS + kq + 3] = f2tf(bv[p].w);
        }
        __syncthreads();

#pragma unroll
        for (int kk = 0; kk < 2; kk++) {
            int kb = kk * 8;
            uint32_t af[4][4], bf[4][2];
#pragma unroll
            for (int mt = 0; mt < 4; mt++) {
                int r0 = (wr * 64 + mt * 16 + g) * GS + kb;
                af[mt][0] = As[r0 + tq];
                af[mt][1] = As[r0 + 8 * GS + tq];
                af[mt][2] = As[r0 + tq + 4];
                af[mt][3] = As[r0 + 8 * GS + tq + 4];
            }
#pragma unroll
            for (int nt = 0; nt < 4; nt++) {
                int c0 = (wc * 32 + nt * 8 + g) * GS + kb;
                bf[nt][0] = Bs[c0 + tq];
                bf[nt][1] = Bs[c0 + tq + 4];
            }
#pragma unroll
            for (int mt = 0; mt < 4; mt++)
#pragma unroll
                for (int nt = 0; nt < 4; nt++)
                    mma8(acc[mt][nt], af[mt], bf[nt]);
        }
    }

    // Epilogue: c0,c1 = row g cols 2tq,2tq+1 ; c2,c3 = row g+8. Pairs = RoPE pairs.
#pragma unroll
    for (int mt = 0; mt < 4; mt++) {
#pragma unroll
        for (int hi = 0; hi < 2; hi++) {
            int row = mBase + wr * 64 + mt * 16 + g + hi * 8;
            int p   = doRope ? pos[row & (S - 1)] : 0;
#pragma unroll
            for (int nt = 0; nt < 4; nt++) {
                float c0 = acc[mt][nt][hi * 2 + 0];
                float c1 = acc[mt][nt][hi * 2 + 1];
                int col = nBase + wc * 32 + nt * 8 + tq * 2;
                if (doRope) {
                    int e = col & 63;   // even in-head index
                    float freq = powf(10000.0f, -(float)e * (1.0f / 64.0f));
                    float sn, cs;
                    sincosf((float)p * freq, &sn, &cs);
                    float v0 = c0, v1 = c1;
                    c0 = cs * v0 - sn * v1;
                    c1 = sn * v0 + cs * v1;
                }
                *(float2*)&C[(size_t)row * D + col] = make_float2(c0, c1);
            }
        }
    }
}

__global__ void __launch_bounds__(256)
qkv_kernel(const float* __restrict__ x,
           const float* __restrict__ WQ,
           const float* __restrict__ WK,
           const float* __restrict__ WV,
           const int* __restrict__ pos)
{
    int z = blockIdx.z;
    const float* W = (z == 0) ? WQ : (z == 1) ? WK : WV;
    float* Cd      = (z == 0) ? g_Q : (z == 1) ? g_K : g_V;
    gemm_tc(x, W, Cd, pos, z < 2);
}

__global__ void __launch_bounds__(256)
oproj_kernel(const float* __restrict__ WO, float* __restrict__ out)
{
    gemm_tc(g_AT, WO, out, nullptr, false);
}

// ---------------------------------------------------------------------------
// Flash attention, tensor-core. Block = (b, h, 128-row q tile), 256 thr.
// Warp w owns q rows w*16..w*16+15 (one m16 tile). KV tiles of 64.
// QK^T: 8 n8-tiles; softmax in C-fragment layout (reduce over 4 lanes);
// P -> tf32 -> smem; PV: 8 d8-tiles.
// smem strides: Qs/Ks/Ps 68 (=4 mod 32), Vs 72 (=8 mod 32) -> conflict-free frags.
// ---------------------------------------------------------------------------
static constexpr int ATT_SMEM_WORDS = 128 * 68 + 64 * 68 + 64 * 72 + 128 * 68; // 26368
static constexpr int ATT_SMEM_BYTES = ATT_SMEM_WORDS * 4;                      // 105472

__global__ void __launch_bounds__(256)
attn_kernel()
{
    extern __shared__ uint32_t smu[];
    uint32_t* Qs = smu;                  // [128][68] tf32 (Q * 0.125)
    uint32_t* Ks = Qs + 128 * 68;        // [64][68]  tf32  (kv pos r, dim k)
    uint32_t* Vs = Ks + 64 * 68;         // [64][72]  tf32  (kv pos r, dim n)
    uint32_t* Ps = Vs + 64 * 72;         // [128][68] tf32

    const int t    = threadIdx.x;
    const int lane = t & 31;
    const int w    = t >> 5;
    const int g    = lane >> 2;
    const int tq   = lane & 3;
    const int qt   = gridDim.x - 1 - blockIdx.x;   // big tiles first
    const int h    = blockIdx.y;
    const int b    = blockIdx.z;

    // ---- load Q tile (128 x 64), scaled by 1/8 ----
    {
        const float* Qg = g_Q + (size_t)(b * S + qt * 128) * D + h * DK;
        int r  = t >> 1;
        int d0 = (t & 1) * 32;
#pragma unroll
        for (int j = 0; j < 8; j++) {
            int dq = d0 + j * 4;
            float4 v = *(const float4*)(Qg + (size_t)r * D + dq);
            Qs[r * 68 + dq + 0] = f2tf(v.x * 0.125f);
            Qs[r * 68 + dq + 1] = f2tf(v.y * 0.125f);
            Qs[r * 68 + dq + 2] = f2tf(v.z * 0.125f);
            Qs[r * 68 + dq + 3] = f2tf(v.w * 0.125f);
        }
    }

    float m0 = -1e30f, m1 = -1e30f, l0 = 0.0f, l1 = 0.0f;
    float oacc[8][4];
#pragma unroll
    for (int dt = 0; dt < 8; dt++)
#pragma unroll
        for (int r = 0; r < 4; r++) oacc[dt][r] = 0.0f;

    const float* Kg = g_K + (size_t)(b * S) * D + h * DK;
    const float* Vg = g_V + (size_t)(b * S) * D + h * DK;

    const int nTiles = 2 * qt + 2;
    const int rowsBase = qt * 128 + w * 16 + g;   // row of c0/c1; +8 for c2/c3

    for (int tt = 0; tt < nTiles; tt++) {
        __syncthreads();
        {   // load K,V tile (64 x 64 each)
            int r  = t >> 2;
            int d0 = (t & 3) * 16;
            const float* Kp = Kg + (size_t)(tt * 64 + r) * D;
            const float* Vp = Vg + (size_t)(tt * 64 + r) * D;
#pragma unroll
            for (int j = 0; j < 4; j++) {
                int dq = d0 + j * 4;
                float4 kv4 = *(const float4*)(Kp + dq);
                float4 vv4 = *(const float4*)(Vp + dq);
                Ks[r * 68 + dq + 0] = f2tf(kv4.x);
                Ks[r * 68 + dq + 1] = f2tf(kv4.y);
                Ks[r * 68 + dq + 2] = f2tf(kv4.z);
                Ks[r * 68 + dq + 3] = f2tf(kv4.w);
                Vs[r * 72 + dq + 0] = f2tf(vv4.x);
                Vs[r * 72 + dq + 1] = f2tf(vv4.y);
                Vs[r * 72 + dq + 2] = f2tf(vv4.z);
                Vs[r * 72 + dq + 3] = f2tf(vv4.w);
            }
        }
        __syncthreads();

        // ---- S = Q K^T ----
        float sc[8][4];
#pragma unroll
        for (int nt = 0; nt < 8; nt++)
#pragma unroll
            for (int r = 0; r < 4; r++) sc[nt][r] = 0.0f;

#pragma unroll
        for (int k8 = 0; k8 < 8; k8++) {
            int kb = k8 * 8;
            uint32_t qf[4];
            int rq = (w * 16 + g) * 68 + kb;
            qf[0] = Qs[rq + tq];
            qf[1] = Qs[rq + 8 * 68 + tq];
            qf[2] = Qs[rq + tq + 4];
            qf[3] = Qs[rq + 8 * 68 + tq + 4];
#pragma unroll
            for (int nt = 0; nt < 8; nt++) {
                int c0 = (nt * 8 + g) * 68 + kb;
                uint32_t bf[2] = { Ks[c0 + tq], Ks[c0 + tq + 4] };
                mma8(sc[nt], qf, bf);
            }
        }

        // ---- causal mask (last two tiles only) ----
        if (tt >= 2 * qt) {
#pragma unroll
            for (int nt = 0; nt < 8; nt++) {
                int col = tt * 64 + nt * 8 + tq * 2;
                if (col > rowsBase)         sc[nt][0] = -1e30f;
                if (col + 1 > rowsBase)     sc[nt][1] = -1e30f;
                if (col > rowsBase + 8)     sc[nt][2] = -1e30f;
                if (col + 1 > rowsBase + 8) sc[nt][3] = -1e30f;
            }
        }

        // ---- online softmax (rows g and g+8; reduce over 4 lanes of group) ----
        float mx0 = -1e30f, mx1 = -1e30f;
#pragma unroll
        for (int nt = 0; nt < 8; nt++) {
            mx0 = fmaxf(mx0, fmaxf(sc[nt][0], sc[nt][1]));
            mx1 = fmaxf(mx1, fmaxf(sc[nt][2], sc[nt][3]));
        }
#pragma unroll
        for (int off = 1; off <= 2; off <<= 1) {
            mx0 = fmaxf(mx0, __shfl_xor_sync(0xffffffffu, mx0, off));
            mx1 = fmaxf(mx1, __shfl_xor_sync(0xffffffffu, mx1, off));
        }
        float mn0 = fmaxf(m0, mx0), mn1 = fmaxf(m1, mx1);
        float a0 = __expf(m0 - mn0), a1 = __expf(m1 - mn1);
        float rs0 = 0.0f, rs1 = 0.0f;
        int prow = (w * 16 + g) * 68;
#pragma unroll
        for (int nt = 0; nt < 8; nt++) {
            float p0 = __expf(sc[nt][0] - mn0);
            float p1 = __expf(sc[nt][1] - mn0);
            float p2 = __expf(sc[nt][2] - mn1);
            float p3 = __expf(sc[nt][3] - mn1);
            rs0 += p0 + p1;
            rs1 += p2 + p3;
            int cc = nt * 8 + tq * 2;
            uint2 u01 = make_uint2(f2tf(p0), f2tf(p1));
            uint2 u23 = make_uint2(f2tf(p2), f2tf(p3));
            *(uint2*)&Ps[prow + cc]          = u01;
            *(uint2*)&Ps[prow + 8 * 68 + cc] = u23;
        }
#pragma unroll
        for (int off = 1; off <= 2; off <<= 1) {
            rs0 += __shfl_xor_sync(0xffffffffu, rs0, off);
            rs1 += __shfl_xor_sync(0xffffffffu, rs1, off);
        }
        l0 = l0 * a0 + rs0;  m0 = mn0;
        l1 = l1 * a1 + rs1;  m1 = mn1;
#pragma unroll
        for (int dt = 0; dt < 8; dt++) {
            oacc[dt][0] *= a0;  oacc[dt][1] *= a0;
            oacc[dt][2] *= a1;  oacc[dt][3] *= a1;
        }
        __syncwarp();

        // ---- O += P V ----
#pragma unroll
        for (int k8 = 0; k8 < 8; k8++) {
            int kb = k8 * 8;
            uint32_t pf[4];
            int rp = (w * 16 + g) * 68 + kb;
            pf[0] = Ps[rp + tq];
            pf[1] = Ps[rp + 8 * 68 + tq];
            pf[2] = Ps[rp + tq + 4];
            pf[3] = Ps[rp + 8 * 68 + tq + 4];
#pragma unroll
            for (int dt = 0; dt < 8; dt++) {
                uint32_t bf[2] = { Vs[(kb + tq) * 72 + dt * 8 + g],
                                   Vs[(kb + tq + 4) * 72 + dt * 8 + g] };
                mma8(oacc[dt], pf, bf);
            }
        }
        __syncwarp();
    }

    // ---- epilogue: normalize, store to g_AT ----
    float inv0 = 1.0f / l0, inv1 = 1.0f / l1;
    float* Og = g_AT + (size_t)(b * S + qt * 128 + w * 16 + g) * D + h * DK;
#pragma unroll
    for (int dt = 0; dt < 8; dt++) {
        int cc = dt * 8 + tq * 2;
        *(float2*)(Og + cc) =
            make_float2(oacc[dt][0] * inv0, oacc[dt][1] * inv0);
        *(float2*)(Og + 8 * (size_t)D + cc) =
            make_float2(oacc[dt][2] * inv1, oacc[dt][3] * inv1);
    }
}

// ---------------------------------------------------------------------------
extern "C" void kernel_launch(void* const* d_in, const int* in_sizes, int n_in,
                              void* d_out, int out_size)
{
    const float* x   = (const float*)d_in[0];
    const int*   pos = (const int*)  d_in[1];
    const float* WQ  = (const float*)d_in[2];
    const float* WK  = (const float*)d_in[3];
    const float* WV  = (const float*)d_in[4];
    const float* WO  = (const float*)d_in[5];
    float* out = (float*)d_out;

    qkv_kernel<<<dim3(D / 128, M / 128, 3), 256>>>(x, WQ, WK, WV, pos);

    cudaFuncSetAttribute(attn_kernel,
                         cudaFuncAttributeMaxDynamicSharedMemorySize,
                         ATT_SMEM_BYTES);
    attn_kernel<<<dim3(S / 128, NH, B), 256, ATT_SMEM_BYTES>>>();

    oproj_kernel<<<dim3(D / 128, M / 128, 1), 256>>>(WO, out);
}

// round 6
// speedup vs baseline: 2.7412x; 1.0247x over previous
#include <cuda_runtime.h>
#include <cstdint>

static constexpr int B  = 2;
static constexpr int S  = 2048;
static constexpr int D  = 1024;
static constexpr int NH = 16;
static constexpr int DK = 64;
static constexpr int M  = B * S;   // 4096

// Scratch (allocation-free rule: __device__ globals)
__device__ float g_Q [M * D];
__device__ float g_K [M * D];
__device__ float g_V [M * D];
__device__ float g_AT[M * D];

// ---------------------------------------------------------------------------
// tf32 helpers
// ---------------------------------------------------------------------------
__device__ __forceinline__ uint32_t f2tf(float f) {
    uint32_t o;
    asm("cvt.rna.tf32.f32 %0, %1;" : "=r"(o) : "f"(f));
    return o;
}

// D += A(16x8 row) * B(8x8 col); c/d fp32
__device__ __forceinline__ void mma8(float* c, const uint32_t* a, const uint32_t* b) {
    asm volatile(
        "mma.sync.aligned.m16n8k8.row.col.f32.tf32.tf32.f32 "
        "{%0,%1,%2,%3}, {%4,%5,%6,%7}, {%8,%9}, {%0,%1,%2,%3};"
        : "+f"(c[0]), "+f"(c[1]), "+f"(c[2]), "+f"(c[3])
        : "r"(a[0]), "r"(a[1]), "r"(a[2]), "r"(a[3]), "r"(b[0]), "r"(b[1]));
}

// ---------------------------------------------------------------------------
// GEMM: C[m][n] = sum_k A[m][k] * W[n][k]   (tf32 tensor-core)
// 128x128 block tile, BK=16, 256 threads = 8 warps in 2x4 (each 64m x 32n).
// 2-stage smem pipeline: LDG(next) || MMA(cur), then STS(next) + one sync.
// smem stride 20 (==20 mod 32) -> fragment loads conflict-free.
// ---------------------------------------------------------------------------
static constexpr int GS    = 20;
static constexpr int STAGE = 128 * GS;   // words per stage per matrix

__device__ __forceinline__ void gemm_tc(const float* __restrict__ A,
                                        const float* __restrict__ W,
                                        float* __restrict__ C,
                                        const int* __restrict__ pos,
                                        bool doRope)
{
    __shared__ uint32_t As[2 * STAGE];
    __shared__ uint32_t Bs[2 * STAGE];

    const int t    = threadIdx.x;
    const int lane = t & 31;
    const int w    = t >> 5;
    const int g    = lane >> 2;     // group (row) id 0..7
    const int tq   = lane & 3;      // thread-in-group 0..3
    const int wr   = w >> 2;        // warp row 0..1 (64 m each)
    const int wc   = w & 3;         // warp col 0..3 (32 n each)
    const int mBase = blockIdx.y * 128;
    const int nBase = blockIdx.x * 128;

    // per-thread load coords (2 slots of 4 floats per matrix)
    const int row0 = t >> 2;                // slot p=0 row
    const int kq0  = (t & 3) * 4;
    const int row1 = (t + 256) >> 2;        // slot p=1 row
    const int kq1  = kq0;                   // (t+256)&3 == t&3

    const float* Ag0 = A + (size_t)(mBase + row0) * D + kq0;
    const float* Ag1 = A + (size_t)(mBase + row1) * D + kq1;
    const float* Wg0 = W + (size_t)(nBase + row0) * D + kq0;
    const float* Wg1 = W + (size_t)(nBase + row1) * D + kq1;

    float acc[4][4][4];
#pragma unroll
    for (int i = 0; i < 4; i++)
#pragma unroll
        for (int j = 0; j < 4; j++)
#pragma unroll
            for (int r = 0; r < 4; r++) acc[i][j][r] = 0.0f;

    float4 av0, av1, bv0, bv1;

    // ---- prologue: stage 0 ----
    av0 = *(const float4*)(Ag0);  av1 = *(const float4*)(Ag1);
    bv0 = *(const float4*)(Wg0);  bv1 = *(const float4*)(Wg1);
    {
        uint32_t* Ad = As;  uint32_t* Bd = Bs;
        *(uint4*)&Ad[row0 * GS + kq0] =
            make_uint4(f2tf(av0.x), f2tf(av0.y), f2tf(av0.z), f2tf(av0.w));
        *(uint4*)&Ad[row1 * GS + kq1] =
            make_uint4(f2tf(av1.x), f2tf(av1.y), f2tf(av1.z), f2tf(av1.w));
        *(uint4*)&Bd[row0 * GS + kq0] =
            make_uint4(f2tf(bv0.x), f2tf(bv0.y), f2tf(bv0.z), f2tf(bv0.w));
        *(uint4*)&Bd[row1 * GS + kq1] =
            make_uint4(f2tf(bv1.x), f2tf(bv1.y), f2tf(bv1.z), f2tf(bv1.w));
    }
    __syncthreads();

    const int NIT = D / 16;   // 64
    for (int it = 0; it < NIT; it++) {
        const int cur = it & 1;

        if (it < NIT - 1) {   // issue next tile's loads early
            int kt = (it + 1) * 16;
            av0 = *(const float4*)(Ag0 + kt);  av1 = *(const float4*)(Ag1 + kt);
            bv0 = *(const float4*)(Wg0 + kt);  bv1 = *(const float4*)(Wg1 + kt);
        }

        const uint32_t* Ac = As + cur * STAGE;
        const uint32_t* Bc = Bs + cur * STAGE;
#pragma unroll
        for (int kk = 0; kk < 2; kk++) {
            int kb = kk * 8;
            uint32_t af[4][4], bf[4][2];
#pragma unroll
            for (int mt = 0; mt < 4; mt++) {
                int r0 = (wr * 64 + mt * 16 + g) * GS + kb;
                af[mt][0] = Ac[r0 + tq];
                af[mt][1] = Ac[r0 + 8 * GS + tq];
                af[mt][2] = Ac[r0 + tq + 4];
                af[mt][3] = Ac[r0 + 8 * GS + tq + 4];
            }
#pragma unroll
            for (int nt = 0; nt < 4; nt++) {
                int c0 = (wc * 32 + nt * 8 + g) * GS + kb;
                bf[nt][0] = Bc[c0 + tq];
                bf[nt][1] = Bc[c0 + tq + 4];
            }
#pragma unroll
            for (int mt = 0; mt < 4; mt++)
#pragma unroll
                for (int nt = 0; nt < 4; nt++)
                    mma8(acc[mt][nt], af[mt], bf[nt]);
        }

        if (it < NIT - 1) {
            uint32_t* Ad = As + (cur ^ 1) * STAGE;
            uint32_t* Bd = Bs + (cur ^ 1) * STAGE;
            *(uint4*)&Ad[row0 * GS + kq0] =
                make_uint4(f2tf(av0.x), f2tf(av0.y), f2tf(av0.z), f2tf(av0.w));
            *(uint4*)&Ad[row1 * GS + kq1] =
                make_uint4(f2tf(av1.x), f2tf(av1.y), f2tf(av1.z), f2tf(av1.w));
            *(uint4*)&Bd[row0 * GS + kq0] =
                make_uint4(f2tf(bv0.x), f2tf(bv0.y), f2tf(bv0.z), f2tf(bv0.w));
            *(uint4*)&Bd[row1 * GS + kq1] =
                make_uint4(f2tf(bv1.x), f2tf(bv1.y), f2tf(bv1.z), f2tf(bv1.w));
            __syncthreads();
        }
    }

    // Epilogue: c0,c1 = row g cols 2tq,2tq+1 ; c2,c3 = row g+8. Pairs = RoPE pairs.
#pragma unroll
    for (int mt = 0; mt < 4; mt++) {
#pragma unroll
        for (int hi = 0; hi < 2; hi++) {
            int row = mBase + wr * 64 + mt * 16 + g + hi * 8;
            int p   = doRope ? pos[row & (S - 1)] : 0;
#pragma unroll
            for (int nt = 0; nt < 4; nt++) {
                float c0 = acc[mt][nt][hi * 2 + 0];
                float c1 = acc[mt][nt][hi * 2 + 1];
                int col = nBase + wc * 32 + nt * 8 + tq * 2;
                if (doRope) {
                    int e = col & 63;   // even in-head index
                    float freq = powf(10000.0f, -(float)e * (1.0f / 64.0f));
                    float sn, cs;
                    sincosf((float)p * freq, &sn, &cs);
                    float v0 = c0, v1 = c1;
                    c0 = cs * v0 - sn * v1;
                    c1 = sn * v0 + cs * v1;
                }
                *(float2*)&C[(size_t)row * D + col] = make_float2(c0, c1);
            }
        }
    }
}

__global__ void __launch_bounds__(256)
qkv_kernel(const float* __restrict__ x,
           const float* __restrict__ WQ,
           const float* __restrict__ WK,
           const float* __restrict__ WV,
           const int* __restrict__ pos)
{
    int z = blockIdx.z;
    const float* W = (z == 0) ? WQ : (z == 1) ? WK : WV;
    float* Cd      = (z == 0) ? g_Q : (z == 1) ? g_K : g_V;
    gemm_tc(x, W, Cd, pos, z < 2);
}

__global__ void __launch_bounds__(256)
oproj_kernel(const float* __restrict__ WO, float* __restrict__ out)
{
    gemm_tc(g_AT, WO, out, nullptr, false);
}

// ---------------------------------------------------------------------------
// Flash attention, tensor-core. Block = (b, h, 128-row q tile), 256 thr.
// Warp w owns q rows w*16..w*16+15 (one m16 tile). KV tiles of 64.
// KV global loads hoisted above the barrier (latency hides in sync wait).
// smem strides: Qs/Ks/Ps 68 (=4 mod 32), Vs 72 (=8 mod 32) -> conflict-free frags.
// ---------------------------------------------------------------------------
static constexpr int ATT_SMEM_WORDS = 128 * 68 + 64 * 68 + 64 * 72 + 128 * 68; // 26368
static constexpr int ATT_SMEM_BYTES = ATT_SMEM_WORDS * 4;                      // 105472

__global__ void __launch_bounds__(256)
attn_kernel()
{
    extern __shared__ uint32_t smu[];
    uint32_t* Qs = smu;                  // [128][68] tf32 (Q * 0.125)
    uint32_t* Ks = Qs + 128 * 68;        // [64][68]  tf32  (kv pos r, dim k)
    uint32_t* Vs = Ks + 64 * 68;         // [64][72]  tf32  (kv pos r, dim n)
    uint32_t* Ps = Vs + 64 * 72;         // [128][68] tf32

    const int t    = threadIdx.x;
    const int lane = t & 31;
    const int w    = t >> 5;
    const int g    = lane >> 2;
    const int tq   = lane & 3;
    const int qt   = gridDim.x - 1 - blockIdx.x;   // big tiles first
    const int h    = blockIdx.y;
    const int b    = blockIdx.z;

    // ---- load Q tile (128 x 64), scaled by 1/8 ----
    {
        const float* Qg = g_Q + (size_t)(b * S + qt * 128) * D + h * DK;
        int r  = t >> 1;
        int d0 = (t & 1) * 32;
#pragma unroll
        for (int j = 0; j < 8; j++) {
            int dq = d0 + j * 4;
            float4 v = *(const float4*)(Qg + (size_t)r * D + dq);
            *(uint4*)&Qs[r * 68 + dq] =
                make_uint4(f2tf(v.x * 0.125f), f2tf(v.y * 0.125f),
                           f2tf(v.z * 0.125f), f2tf(v.w * 0.125f));
        }
    }

    float m0 = -1e30f, m1 = -1e30f, l0 = 0.0f, l1 = 0.0f;
    float oacc[8][4];
#pragma unroll
    for (int dt = 0; dt < 8; dt++)
#pragma unroll
        for (int r = 0; r < 4; r++) oacc[dt][r] = 0.0f;

    const float* Kg = g_K + (size_t)(b * S) * D + h * DK;
    const float* Vg = g_V + (size_t)(b * S) * D + h * DK;

    const int nTiles = 2 * qt + 2;
    const int rowsBase = qt * 128 + w * 16 + g;   // row of c0/c1; +8 for c2/c3

    const int lr  = t >> 2;          // kv row this thread loads
    const int ld0 = (t & 3) * 16;    // kv dim base

    for (int tt = 0; tt < nTiles; tt++) {
        // ---- issue KV loads BEFORE the barrier: latency overlaps sync wait ----
        float4 kreg[4], vreg[4];
        {
            const float* Kp = Kg + (size_t)(tt * 64 + lr) * D + ld0;
            const float* Vp = Vg + (size_t)(tt * 64 + lr) * D + ld0;
#pragma unroll
            for (int j = 0; j < 4; j++) {
                kreg[j] = *(const float4*)(Kp + j * 4);
                vreg[j] = *(const float4*)(Vp + j * 4);
            }
        }
        __syncthreads();   // previous tile's smem reads done
#pragma unroll
        for (int j = 0; j < 4; j++) {
            int dq = ld0 + j * 4;
            *(uint4*)&Ks[lr * 68 + dq] =
                make_uint4(f2tf(kreg[j].x), f2tf(kreg[j].y),
                           f2tf(kreg[j].z), f2tf(kreg[j].w));
            *(uint4*)&Vs[lr * 72 + dq] =
                make_uint4(f2tf(vreg[j].x), f2tf(vreg[j].y),
                           f2tf(vreg[j].z), f2tf(vreg[j].w));
        }
        __syncthreads();

        // ---- S = Q K^T ----
        float sc[8][4];
#pragma unroll
        for (int nt = 0; nt < 8; nt++)
#pragma unroll
            for (int r = 0; r < 4; r++) sc[nt][r] = 0.0f;

#pragma unroll
        for (int k8 = 0; k8 < 8; k8++) {
            int kb = k8 * 8;
            uint32_t qf[4];
            int rq = (w * 16 + g) * 68 + kb;
            qf[0] = Qs[rq + tq];
            qf[1] = Qs[rq + 8 * 68 + tq];
            qf[2] = Qs[rq + tq + 4];
            qf[3] = Qs[rq + 8 * 68 + tq + 4];
#pragma unroll
            for (int nt = 0; nt < 8; nt++) {
                int c0 = (nt * 8 + g) * 68 + kb;
                uint32_t bf[2] = { Ks[c0 + tq], Ks[c0 + tq + 4] };
                mma8(sc[nt], qf, bf);
            }
        }

        // ---- causal mask (last two tiles only) ----
        if (tt >= 2 * qt) {
#pragma unroll
            for (int nt = 0; nt < 8; nt++) {
                int col = tt * 64 + nt * 8 + tq * 2;
                if (col > rowsBase)         sc[nt][0] = -1e30f;
                if (col + 1 > rowsBase)     sc[nt][1] = -1e30f;
                if (col > rowsBase + 8)     sc[nt][2] = -1e30f;
                if (col + 1 > rowsBase + 8) sc[nt][3] = -1e30f;
            }
        }

        // ---- online softmax (rows g and g+8; reduce over 4 lanes of group) ----
        float mx0 = -1e30f, mx1 = -1e30f;
#pragma unroll
        for (int nt = 0; nt < 8; nt++) {
            mx0 = fmaxf(mx0, fmaxf(sc[nt][0], sc[nt][1]));
            mx1 = fmaxf(mx1, fmaxf(sc[nt][2], sc[nt][3]));
        }
#pragma unroll
        for (int off = 1; off <= 2; off <<= 1) {
            mx0 = fmaxf(mx0, __shfl_xor_sync(0xffffffffu, mx0, off));
            mx1 = fmaxf(mx1, __shfl_xor_sync(0xffffffffu, mx1, off));
        }
        float mn0 = fmaxf(m0, mx0), mn1 = fmaxf(m1, mx1);
        float a0 = __expf(m0 - mn0), a1 = __expf(m1 - mn1);
        float rs0 = 0.0f, rs1 = 0.0f;
        int prow = (w * 16 + g) * 68;
#pragma unroll
        for (int nt = 0; nt < 8; nt++) {
            float p0 = __expf(sc[nt][0] - mn0);
            float p1 = __expf(sc[nt][1] - mn0);
            float p2 = __expf(sc[nt][2] - mn1);
            float p3 = __expf(sc[nt][3] - mn1);
            rs0 += p0 + p1;
            rs1 += p2 + p3;
            int cc = nt * 8 + tq * 2;
            *(uint2*)&Ps[prow + cc]          = make_uint2(f2tf(p0), f2tf(p1));
            *(uint2*)&Ps[prow + 8 * 68 + cc] = make_uint2(f2tf(p2), f2tf(p3));
        }
#pragma unroll
        for (int off = 1; off <= 2; off <<= 1) {
            rs0 += __shfl_xor_sync(0xffffffffu, rs0, off);
            rs1 += __shfl_xor_sync(0xffffffffu, rs1, off);
        }
        l0 = l0 * a0 + rs0;  m0 = mn0;
        l1 = l1 * a1 + rs1;  m1 = mn1;
#pragma unroll
        for (int dt = 0; dt < 8; dt++) {
            oacc[dt][0] *= a0;  oacc[dt][1] *= a0;
            oacc[dt][2] *= a1;  oacc[dt][3] *= a1;
        }
        __syncwarp();

        // ---- O += P V ----
#pragma unroll
        for (int k8 = 0; k8 < 8; k8++) {
            int kb = k8 * 8;
            uint32_t pf[4];
            int rp = (w * 16 + g) * 68 + kb;
            pf[0] = Ps[rp + tq];
            pf[1] = Ps[rp + 8 * 68 + tq];
            pf[2] = Ps[rp + tq + 4];
            pf[3] = Ps[rp + 8 * 68 + tq + 4];
#pragma unroll
            for (int dt = 0; dt < 8; dt++) {
                uint32_t bf[2] = { Vs[(kb + tq) * 72 + dt * 8 + g],
                                   Vs[(kb + tq + 4) * 72 + dt * 8 + g] };
                mma8(oacc[dt], pf, bf);
            }
        }
        __syncwarp();
    }

    // ---- epilogue: normalize, store to g_AT ----
    float inv0 = 1.0f / l0, inv1 = 1.0f / l1;
    float* Og = g_AT + (size_t)(b * S + qt * 128 + w * 16 + g) * D + h * DK;
#pragma unroll
    for (int dt = 0; dt < 8; dt++) {
        int cc = dt * 8 + tq * 2;
        *(float2*)(Og + cc) =
            make_float2(oacc[dt][0] * inv0, oacc[dt][1] * inv0);
        *(float2*)(Og + 8 * (size_t)D + cc) =
            make_float2(oacc[dt][2] * inv1, oacc[dt][3] * inv1);
    }
}

// ---------------------------------------------------------------------------
extern "C" void kernel_launch(void* const* d_in, const int* in_sizes, int n_in,
                              void* d_out, int out_size)
{
    const float* x   = (const float*)d_in[0];
    const int*   pos = (const int*)  d_in[1];
    const float* WQ  = (const float*)d_in[2];
    const float* WK  = (const float*)d_in[3];
    const float* WV  = (const float*)d_in[4];
    const float* WO  = (const float*)d_in[5];
    float* out = (float*)d_out;

    qkv_kernel<<<dim3(D / 128, M / 128, 3), 256>>>(x, WQ, WK, WV, pos);

    cudaFuncSetAttribute(attn_kernel,
                         cudaFuncAttributeMaxDynamicSharedMemorySize,
                         ATT_SMEM_BYTES);
    attn_kernel<<<dim3(S / 128, NH, B), 256, ATT_SMEM_BYTES>>>();

    oproj_kernel<<<dim3(D / 128, M / 128, 1), 256>>>(WO, out);
}

// round 9
// speedup vs baseline: 2.7706x; 1.0107x over previous
#include <cuda_runtime.h>
#include <cstdint>

static constexpr int B  = 2;
static constexpr int S  = 2048;
static constexpr int D  = 1024;
static constexpr int NH = 16;
static constexpr int DK = 64;
static constexpr int M  = B * S;   // 4096

// Scratch (allocation-free rule: __device__ globals)
__device__ float g_Q  [M * D];
__device__ float g_K  [M * D];
__device__ float g_V  [M * D];
__device__ float g_AT [M * D];
// tf32-pre-rounded copies of inputs
__device__ float g_xr [M * D];
__device__ float g_WQr[D * D];
__device__ float g_WKr[D * D];
__device__ float g_WVr[D * D];
__device__ float g_WOr[D * D];

// ---------------------------------------------------------------------------
// helpers
// ---------------------------------------------------------------------------
__device__ __forceinline__ uint32_t f2tf(float f) {
    uint32_t o;
    asm("cvt.rna.tf32.f32 %0, %1;" : "=r"(o) : "f"(f));
    return o;
}
__device__ __forceinline__ float f2tff(float f) { return __uint_as_float(f2tf(f)); }

// D += A(16x8 row) * B(8x8 col); c/d fp32, a/b tf32 bit patterns
__device__ __forceinline__ void mma8(float* c, const uint32_t* a, const uint32_t* b) {
    asm volatile(
        "mma.sync.aligned.m16n8k8.row.col.f32.tf32.tf32.f32 "
        "{%0,%1,%2,%3}, {%4,%5,%6,%7}, {%8,%9}, {%0,%1,%2,%3};"
        : "+f"(c[0]), "+f"(c[1]), "+f"(c[2]), "+f"(c[3])
        : "r"(a[0]), "r"(a[1]), "r"(a[2]), "r"(a[3]), "r"(b[0]), "r"(b[1]));
}

__device__ __forceinline__ void cp16(uint32_t smem_dst, const void* gsrc) {
    asm volatile("cp.async.cg.shared.global [%0], [%1], 16;"
                 :: "r"(smem_dst), "l"(gsrc));
}
__device__ __forceinline__ void cp_commit() {
    asm volatile("cp.async.commit_group;" ::: "memory");
}
template <int N>
__device__ __forceinline__ void cp_wait() {
    asm volatile("cp.async.wait_group %0;" :: "n"(N) : "memory");
}

// ---------------------------------------------------------------------------
// input pre-rounding (tf32 rna) — makes GMEM data tf32-clean so GEMMs can
// cp.async raw bits straight into smem with numerics identical to cvt-at-STS.
// ---------------------------------------------------------------------------
__global__ void __launch_bounds__(256)
round_kernel(const float* __restrict__ src, float* __restrict__ dst, int n4)
{
    int i = blockIdx.x * 256 + threadIdx.x;
    if (i < n4) {
        float4 v = ((const float4*)src)[i];
        ((float4*)dst)[i] = make_float4(f2tff(v.x), f2tff(v.y),
                                        f2tff(v.z), f2tff(v.w));
    }
}

// ---------------------------------------------------------------------------
// GEMM: C[m][n] = sum_k A[m][k] * W[n][k]   (tf32 tensor-core)
// 128x128 tile, BK=16, 256 threads = 8 warps (2x4, each 64m x 32n).
// 3-stage cp.async pipeline; A/W must be tf32-pre-rounded.
// smem stride 20 (==20 mod 32) -> fragment LDS conflict-free.
// ---------------------------------------------------------------------------
static constexpr int GS      = 20;
static constexpr int STAGE   = 128 * GS;                    // words / stage / matrix
static constexpr int GEMM_SMEM_BYTES = 3 * 2 * STAGE * 4;   // 61440

__device__ __forceinline__ void gemm_tc(const float* __restrict__ A,
                                        const float* __restrict__ W,
                                        float* __restrict__ C,
                                        const int* __restrict__ pos,
                                        bool doRope, bool roundOut)
{
    extern __shared__ uint32_t smg[];
    uint32_t* As = smg;                 // 3 stages
    uint32_t* Bs = smg + 3 * STAGE;     // 3 stages

    const int t    = threadIdx.x;
    const int lane = t & 31;
    const int w    = t >> 5;
    const int g    = lane >> 2;
    const int tq   = lane & 3;
    const int wr   = w >> 2;
    const int wc   = w & 3;
    const int mBase = blockIdx.y * 128;
    const int nBase = blockIdx.x * 128;

    // per-thread cp.async coords: 2 chunks of 16B per matrix per stage
    const int row0 = t >> 2;          // 0..63
    const int row1 = row0 + 64;       // 64..127
    const int kq   = (t & 3) * 4;

    const float* Ag0 = A + (size_t)(mBase + row0) * D + kq;
    const float* Ag1 = A + (size_t)(mBase + row1) * D + kq;
    const float* Wg0 = W + (size_t)(nBase + row0) * D + kq;
    const float* Wg1 = W + (size_t)(nBase + row1) * D + kq;

    const uint32_t sA0 = (uint32_t)__cvta_generic_to_shared(&As[row0 * GS + kq]);
    const uint32_t sA1 = (uint32_t)__cvta_generic_to_shared(&As[row1 * GS + kq]);
    const uint32_t sB0 = (uint32_t)__cvta_generic_to_shared(&Bs[row0 * GS + kq]);
    const uint32_t sB1 = (uint32_t)__cvta_generic_to_shared(&Bs[row1 * GS + kq]);
    const uint32_t stageB = STAGE * 4;   // bytes

    float acc[4][4][4];
#pragma unroll
    for (int i = 0; i < 4; i++)
#pragma unroll
        for (int j = 0; j < 4; j++)
#pragma unroll
            for (int r = 0; r < 4; r++) acc[i][j][r] = 0.0f;

    const int NIT = D / 16;   // 64

    // prologue: stages 0 and 1
#pragma unroll
    for (int s = 0; s < 2; s++) {
        int kt = s * 16;
        cp16(sA0 + s * stageB, Ag0 + kt);
        cp16(sA1 + s * stageB, Ag1 + kt);
        cp16(sB0 + s * stageB, Wg0 + kt);
        cp16(sB1 + s * stageB, Wg1 + kt);
        cp_commit();
    }

    for (int it = 0; it < NIT; it++) {
        cp_wait<1>();        // stage `it` complete (one newer may pend)
        __syncthreads();     // visibility + buffer (it+2)%3 free

        {   // issue stage it+2 (empty commit keeps group accounting uniform)
            int s = it + 2;
            if (s < NIT) {
                int buf = s % 3;
                int kt  = s * 16;
                cp16(sA0 + buf * stageB, Ag0 + kt);
                cp16(sA1 + buf * stageB, Ag1 + kt);
                cp16(sB0 + buf * stageB, Wg0 + kt);
                cp16(sB1 + buf * stageB, Wg1 + kt);
            }
            cp_commit();
        }

        const uint32_t* Ac = As + (it % 3) * STAGE;
        const uint32_t* Bc = Bs + (it % 3) * STAGE;
#pragma unroll
        for (int kk = 0; kk < 2; kk++) {
            int kb = kk * 8;
            uint32_t af[4][4], bf[4][2];
#pragma unroll
            for (int mt = 0; mt < 4; mt++) {
                int r0 = (wr * 64 + mt * 16 + g) * GS + kb;
                af[mt][0] = Ac[r0 + tq];
                af[mt][1] = Ac[r0 + 8 * GS + tq];
                af[mt][2] = Ac[r0 + tq + 4];
                af[mt][3] = Ac[r0 + 8 * GS + tq + 4];
            }
#pragma unroll
            for (int nt = 0; nt < 4; nt++) {
                int c0 = (wc * 32 + nt * 8 + g) * GS + kb;
                bf[nt][0] = Bc[c0 + tq];
                bf[nt][1] = Bc[c0 + tq + 4];
            }
#pragma unroll
            for (int mt = 0; mt < 4; mt++)
#pragma unroll
                for (int nt = 0; nt < 4; nt++)
                    mma8(acc[mt][nt], af[mt], bf[nt]);
        }
    }

    // Epilogue. c0,c1 = row g cols 2tq,2tq+1; c2,c3 = row g+8. Pairs = RoPE pairs.
#pragma unroll
    for (int mt = 0; mt < 4; mt++) {
#pragma unroll
        for (int hi = 0; hi < 2; hi++) {
            int row = mBase + wr * 64 + mt * 16 + g + hi * 8;
            int p   = doRope ? pos[row & (S - 1)] : 0;
#pragma unroll
            for (int nt = 0; nt < 4; nt++) {
                float c0 = acc[mt][nt][hi * 2 + 0];
                float c1 = acc[mt][nt][hi * 2 + 1];
                int col = nBase + wc * 32 + nt * 8 + tq * 2;
                if (doRope) {
                    int e = col & 63;
                    float freq = powf(10000.0f, -(float)e * (1.0f / 64.0f));
                    float sn, cs;
                    sincosf((float)p * freq, &sn, &cs);
                    float v0 = c0, v1 = c1;
                    c0 = cs * v0 - sn * v1;
                    c1 = sn * v0 + cs * v1;
                }
                if (roundOut) { c0 = f2tff(c0); c1 = f2tff(c1); }
                *(float2*)&C[(size_t)row * D + col] = make_float2(c0, c1);
            }
        }
    }
}

__global__ void __launch_bounds__(256)
qkv_kernel(const int* __restrict__ pos)
{
    int z = blockIdx.z;
    const float* W = (z == 0) ? g_WQr : (z == 1) ? g_WKr : g_WVr;
    float* Cd      = (z == 0) ? g_Q   : (z == 1) ? g_K   : g_V;
    gemm_tc(g_xr, W, Cd, pos, z < 2, true);   // outputs rounded for attn
}

__global__ void __launch_bounds__(256)
oproj_kernel(float* __restrict__ out)
{
    gemm_tc(g_AT, g_WOr, out, nullptr, false, false);
}

// ---------------------------------------------------------------------------
// Flash attention, tensor-core. Block = (b, h, 128-row q tile), 256 thr.
// Q/K/V are tf32-pre-rounded by qkv epilogue -> raw bit staging, no cvt.
// smem strides: Qs/Ks/Ps 68 (=4 mod 32), Vs 72 (=8 mod 32) -> conflict-free.
// ---------------------------------------------------------------------------
static constexpr int ATT_SMEM_WORDS = 128 * 68 + 64 * 68 + 64 * 72 + 128 * 68;
static constexpr int ATT_SMEM_BYTES = ATT_SMEM_WORDS * 4;   // 105472

__global__ void __launch_bounds__(256)
attn_kernel()
{
    extern __shared__ uint32_t smu[];
    uint32_t* Qs = smu;                  // [128][68]
    uint32_t* Ks = Qs + 128 * 68;        // [64][68]
    uint32_t* Vs = Ks + 64 * 68;         // [64][72]
    uint32_t* Ps = Vs + 64 * 72;         // [128][68]

    const int t    = threadIdx.x;
    const int lane = t & 31;
    const int w    = t >> 5;
    const int g    = lane >> 2;
    const int tq   = lane & 3;
    const int qt   = gridDim.x - 1 - blockIdx.x;   // big tiles first
    const int h    = blockIdx.y;
    const int b    = blockIdx.z;

    // ---- load Q tile (128 x 64), scale by 1/8 (exact exponent shift) ----
    {
        const float* Qg = g_Q + (size_t)(b * S + qt * 128) * D + h * DK;
        int r  = t >> 1;
        int d0 = (t & 1) * 32;
#pragma unroll
        for (int j = 0; j < 8; j++) {
            int dq = d0 + j * 4;
            float4 v = *(const float4*)(Qg + (size_t)r * D + dq);
            *(uint4*)&Qs[r * 68 + dq] =
                make_uint4(__float_as_uint(v.x * 0.125f), __float_as_uint(v.y * 0.125f),
                           __float_as_uint(v.z * 0.125f), __float_as_uint(v.w * 0.125f));
        }
    }

    float m0 = -1e30f, m1 = -1e30f, l0 = 0.0f, l1 = 0.0f;
    float oacc[8][4];
#pragma unroll
    for (int dt = 0; dt < 8; dt++)
#pragma unroll
        for (int r = 0; r < 4; r++) oacc[dt][r] = 0.0f;

    const float* Kg = g_K + (size_t)(b * S) * D + h * DK;
    const float* Vg = g_V + (size_t)(b * S) * D + h * DK;

    const int nTiles   = 2 * qt + 2;
    const int rowsBase = qt * 128 + w * 16 + g;

    const int lr  = t >> 2;
    const int ld0 = (t & 3) * 16;

    for (int tt = 0; tt < nTiles; tt++) {
        // issue KV loads BEFORE the barrier: latency overlaps sync wait
        uint4 kreg[4], vreg[4];
        {
            const float* Kp = Kg + (size_t)(tt * 64 + lr) * D + ld0;
            const float* Vp = Vg + (size_t)(tt * 64 + lr) * D + ld0;
#pragma unroll
            for (int j = 0; j < 4; j++) {
                kreg[j] = *(const uint4*)(Kp + j * 4);
                vreg[j] = *(const uint4*)(Vp + j * 4);
            }
        }
        __syncthreads();
#pragma unroll
        for (int j = 0; j < 4; j++) {
            int dq = ld0 + j * 4;
            *(uint4*)&Ks[lr * 68 + dq] = kreg[j];
            *(uint4*)&Vs[lr * 72 + dq] = vreg[j];
        }
        __syncthreads();

        // ---- S = Q K^T ----
        float sc[8][4];
#pragma unroll
        for (int nt = 0; nt < 8; nt++)
#pragma unroll
            for (int r = 0; r < 4; r++) sc[nt][r] = 0.0f;

#pragma unroll
        for (int k8 = 0; k8 < 8; k8++) {
            int kb = k8 * 8;
            uint32_t qf[4];
            int rq = (w * 16 + g) * 68 + kb;
            qf[0] = Qs[rq + tq];
            qf[1] = Qs[rq + 8 * 68 + tq];
            qf[2] = Qs[rq + tq + 4];
            qf[3] = Qs[rq + 8 * 68 + tq + 4];
#pragma unroll
            for (int nt = 0; nt < 8; nt++) {
                int c0 = (nt * 8 + g) * 68 + kb;
                uint32_t bf[2] = { Ks[c0 + tq], Ks[c0 + tq + 4] };
                mma8(sc[nt], qf, bf);
            }
        }

        // ---- causal mask (last two tiles only) ----
        if (tt >= 2 * qt) {
#pragma unroll
            for (int nt = 0; nt < 8; nt++) {
                int col = tt * 64 + nt * 8 + tq * 2;
                if (col > rowsBase)         sc[nt][0] = -1e30f;
                if (col + 1 > rowsBase)     sc[nt][1] = -1e30f;
                if (col > rowsBase + 8)     sc[nt][2] = -1e30f;
                if (col + 1 > rowsBase + 8) sc[nt][3] = -1e30f;
            }
        }

        // ---- online softmax (rows g and g+8; reduce over 4 lanes) ----
        float mx0 = -1e30f, mx1 = -1e30f;
#pragma unroll
        for (int nt = 0; nt < 8; nt++) {
            mx0 = fmaxf(mx0, fmaxf(sc[nt][0], sc[nt][1]));
            mx1 = fmaxf(mx1, fmaxf(sc[nt][2], sc[nt][3]));
        }
#pragma unroll
        for (int off = 1; off <= 2; off <<= 1) {
            mx0 = fmaxf(mx0, __shfl_xor_sync(0xffffffffu, mx0, off));
            mx1 = fmaxf(mx1, __shfl_xor_sync(0xffffffffu, mx1, off));
        }
        float mn0 = fmaxf(m0, mx0), mn1 = fmaxf(m1, mx1);
        float a0 = __expf(m0 - mn0), a1 = __expf(m1 - mn1);
        float rs0 = 0.0f, rs1 = 0.0f;
        int prow = (w * 16 + g) * 68;
#pragma unroll
        for (int nt = 0; nt < 8; nt++) {
            float p0 = __expf(sc[nt][0] - mn0);
            float p1 = __expf(sc[nt][1] - mn0);
            float p2 = __expf(sc[nt][2] - mn1);
            float p3 = __expf(sc[nt][3] - mn1);
            rs0 += p0 + p1;
            rs1 += p2 + p3;
            int cc = nt * 8 + tq * 2;
            *(uint2*)&Ps[prow + cc]          = make_uint2(f2tf(p0), f2tf(p1));
            *(uint2*)&Ps[prow + 8 * 68 + cc] = make_uint2(f2tf(p2), f2tf(p3));
        }
#pragma unroll
        for (int off = 1; off <= 2; off <<= 1) {
            rs0 += __shfl_xor_sync(0xffffffffu, rs0, off);
            rs1 += __shfl_xor_sync(0xffffffffu, rs1, off);
        }
        l0 = l0 * a0 + rs0;  m0 = mn0;
        l1 = l1 * a1 + rs1;  m1 = mn1;
#pragma unroll
        for (int dt = 0; dt < 8; dt++) {
            oacc[dt][0] *= a0;  oacc[dt][1] *= a0;
            oacc[dt][2] *= a1;  oacc[dt][3] *= a1;
        }
        __syncwarp();

        // ---- O += P V ----
#pragma unroll
        for (int k8 = 0; k8 < 8; k8++) {
            int kb = k8 * 8;
            uint32_t pf[4];
            int rp = (w * 16 + g) * 68 + kb;
            pf[0] = Ps[rp + tq];
            pf[1] = Ps[rp + 8 * 68 + tq];
            pf[2] = Ps[rp + tq + 4];
            pf[3] = Ps[rp + 8 * 68 + tq + 4];
#pragma unroll
            for (int dt = 0; dt < 8; dt++) {
                uint32_t bf[2] = { Vs[(kb + tq) * 72 + dt * 8 + g],
                                   Vs[(kb + tq + 4) * 72 + dt * 8 + g] };
                mma8(oacc[dt], pf, bf);
            }
        }
        __syncwarp();
    }

    // ---- epilogue: normalize, round (feeds oproj), store ----
    float inv0 = 1.0f / l0, inv1 = 1.0f / l1;
    float* Og = g_AT + (size_t)(b * S + qt * 128 + w * 16 + g) * D + h * DK;
#pragma unroll
    for (int dt = 0; dt < 8; dt++) {
        int cc = dt * 8 + tq * 2;
        *(float2*)(Og + cc) =
            make_float2(f2tff(oacc[dt][0] * inv0), f2tff(oacc[dt][1] * inv0));
        *(float2*)(Og + 8 * (size_t)D + cc) =
            make_float2(f2tff(oacc[dt][2] * inv1), f2tff(oacc[dt][3] * inv1));
    }
}

// ---------------------------------------------------------------------------
extern "C" void kernel_launch(void* const* d_in, const int* in_sizes, int n_in,
                              void* d_out, int out_size)
{
    const float* x   = (const float*)d_in[0];
    const int*   pos = (const int*)  d_in[1];
    const float* WQ  = (const float*)d_in[2];
    const float* WK  = (const float*)d_in[3];
    const float* WV  = (const float*)d_in[4];
    const float* WO  = (const float*)d_in[5];
    float* out = (float*)d_out;

    float *xr, *wqr, *wkr, *wvr, *wor;
    cudaGetSymbolAddress((void**)&xr,  g_xr);
    cudaGetSymbolAddress((void**)&wqr, g_WQr);
    cudaGetSymbolAddress((void**)&wkr, g_WKr);
    cudaGetSymbolAddress((void**)&wvr, g_WVr);
    cudaGetSymbolAddress((void**)&wor, g_WOr);

    round_kernel<<<(M * D / 4 + 255) / 256, 256>>>(x,  xr,  M * D / 4);
    round_kernel<<<(D * D / 4 + 255) / 256, 256>>>(WQ, wqr, D * D / 4);
    round_kernel<<<(D * D / 4 + 255) / 256, 256>>>(WK, wkr, D * D / 4);
    round_kernel<<<(D * D / 4 + 255) / 256, 256>>>(WV, wvr, D * D / 4);
    round_kernel<<<(D * D / 4 + 255) / 256, 256>>>(WO, wor, D * D / 4);

    cudaFuncSetAttribute(qkv_kernel,
                         cudaFuncAttributeMaxDynamicSharedMemorySize,
                         GEMM_SMEM_BYTES);
    cudaFuncSetAttribute(oproj_kernel,
                         cudaFuncAttributeMaxDynamicSharedMemorySize,
                         GEMM_SMEM_BYTES);
    cudaFuncSetAttribute(attn_kernel,
                         cudaFuncAttributeMaxDynamicSharedMemorySize,
                         ATT_SMEM_BYTES);

    qkv_kernel<<<dim3(D / 128, M / 128, 3), 256, GEMM_SMEM_BYTES>>>(pos);
    attn_kernel<<<dim3(S / 128, NH, B), 256, ATT_SMEM_BYTES>>>();
    oproj_kernel<<<dim3(D / 128, M / 128, 1), 256, GEMM_SMEM_BYTES>>>(out);
}

// round 12
// speedup vs baseline: 5.2426x; 1.8922x over previous
#include <cuda_runtime.h>
#include <cuda_fp16.h>
#include <cstdint>

static constexpr int B  = 2;
static constexpr int S  = 2048;
static constexpr int D  = 1024;
static constexpr int NH = 16;
static constexpr int DK = 64;
static constexpr int M  = B * S;   // 4096

// Scratch (allocation-free rule: __device__ globals) — all fp16 now
__device__ __half g_Qh [M * D];
__device__ __half g_Kh [M * D];
__device__ __half g_Vh [M * D];
__device__ __half g_ATh[M * D];
__device__ __half g_xh [M * D];
__device__ __half g_WQh[D * D];
__device__ __half g_WKh[D * D];
__device__ __half g_WVh[D * D];
__device__ __half g_WOh[D * D];

// ---------------------------------------------------------------------------
// helpers
// ---------------------------------------------------------------------------
// D(16x8,f32) += A(16x16 f16 row) * B(16x8 f16 col)
__device__ __forceinline__ void mma16(float* c, const uint32_t* a, const uint32_t* b) {
    asm volatile(
        "mma.sync.aligned.m16n8k16.row.col.f32.f16.f16.f32 "
        "{%0,%1,%2,%3}, {%4,%5,%6,%7}, {%8,%9}, {%0,%1,%2,%3};"
        : "+f"(c[0]), "+f"(c[1]), "+f"(c[2]), "+f"(c[3])
        : "r"(a[0]), "r"(a[1]), "r"(a[2]), "r"(a[3]), "r"(b[0]), "r"(b[1]));
}

__device__ __forceinline__ void ldsm_x4_trans(uint32_t& r0, uint32_t& r1,
                                              uint32_t& r2, uint32_t& r3,
                                              uint32_t addr) {
    asm volatile(
        "ldmatrix.sync.aligned.m8n8.x4.trans.shared.b16 {%0,%1,%2,%3}, [%4];"
        : "=r"(r0), "=r"(r1), "=r"(r2), "=r"(r3) : "r"(addr));
}

__device__ __forceinline__ void cp16(uint32_t smem_dst, const void* gsrc) {
    asm volatile("cp.async.cg.shared.global [%0], [%1], 16;"
                 :: "r"(smem_dst), "l"(gsrc));
}
__device__ __forceinline__ void cp_commit() {
    asm volatile("cp.async.commit_group;" ::: "memory");
}
template <int N>
__device__ __forceinline__ void cp_wait() {
    asm volatile("cp.async.wait_group %0;" :: "n"(N) : "memory");
}

__device__ __forceinline__ uint32_t h2u(__half2 h) {
    return *reinterpret_cast<uint32_t*>(&h);
}

// ---------------------------------------------------------------------------
// fp32 -> fp16 input conversion
// ---------------------------------------------------------------------------
__global__ void __launch_bounds__(256)
tohalf_kernel(const float* __restrict__ src, __half* __restrict__ dst, int n4)
{
    int i = blockIdx.x * 256 + threadIdx.x;
    if (i < n4) {
        float4 v = ((const float4*)src)[i];
        uint2 o;
        o.x = h2u(__floats2half2_rn(v.x, v.y));
        o.y = h2u(__floats2half2_rn(v.z, v.w));
        ((uint2*)dst)[i] = o;
    }
}

__global__ void __launch_bounds__(256)
tohalfW_kernel(const float* __restrict__ WQ, const float* __restrict__ WK,
               const float* __restrict__ WV, const float* __restrict__ WO)
{
    int z = blockIdx.y;
    const float* s = (z == 0) ? WQ : (z == 1) ? WK : (z == 2) ? WV : WO;
    __half*      d = (z == 0) ? g_WQh : (z == 1) ? g_WKh : (z == 2) ? g_WVh : g_WOh;
    int i = blockIdx.x * 256 + threadIdx.x;
    float4 v = ((const float4*)s)[i];
    uint2 o;
    o.x = h2u(__floats2half2_rn(v.x, v.y));
    o.y = h2u(__floats2half2_rn(v.z, v.w));
    ((uint2*)d)[i] = o;
}

// ---------------------------------------------------------------------------
// fp16 GEMM: C[m][n] = sum_k A[m][k] * W[n][k]
// 128x128 tile, BK=32 halves, 256 threads = 8 warps (2x4, each 64m x 32n).
// 3-stage cp.async pipeline. smem rows: 40 halves (20 uints, 80B) — fragment
// half2 loads land on banks 20g+tq (mod 32): conflict-free.
// ---------------------------------------------------------------------------
static constexpr int HKS    = 20;           // uints per row (32 data + 8 pad halves)
static constexpr int HSTAGE = 128 * HKS;    // uints per matrix per stage (2560)
static constexpr int GEMM_SMEM_BYTES = 3 * 2 * HSTAGE * 4;   // 61440

__device__ __forceinline__ void gemm_h(const __half* __restrict__ A,
                                       const __half* __restrict__ W,
                                       void* __restrict__ Cout, bool halfOut,
                                       const int* __restrict__ pos,
                                       bool doRope, bool scaleQ)
{
    extern __shared__ uint32_t smg[];
    const uint32_t sbase = (uint32_t)__cvta_generic_to_shared(smg);

    const int t    = threadIdx.x;
    const int lane = t & 31;
    const int w    = t >> 5;
    const int g    = lane >> 2;
    const int tq   = lane & 3;
    const int wr   = w >> 2;          // 0..1 (64 m)
    const int wc   = w & 3;           // 0..3 (32 n)
    const int mBase = blockIdx.y * 128;
    const int nBase = blockIdx.x * 128;

    // staging: thread -> row t>>1, chunk pair (t&1)*2
    const int srow = t >> 1;
    const int sc0  = (t & 1) * 2;
    const __half* Ag = A + (size_t)(mBase + srow) * D + sc0 * 8;
    const __half* Wg = W + (size_t)(nBase + srow) * D + sc0 * 8;
    const uint32_t rowOff = (uint32_t)(srow * HKS * 4 + sc0 * 16);

    float acc[4][4][4];
#pragma unroll
    for (int i = 0; i < 4; i++)
#pragma unroll
        for (int j = 0; j < 4; j++)
#pragma unroll
            for (int r = 0; r < 4; r++) acc[i][j][r] = 0.0f;

    const int NIT = D / 32;   // 32 stages

#pragma unroll
    for (int s = 0; s < 2; s++) {   // prologue
        uint32_t ab = sbase + (uint32_t)(s * 2 * HSTAGE) * 4 + rowOff;
        cp16(ab,      Ag + s * 32);
        cp16(ab + 16, Ag + s * 32 + 8);
        uint32_t bb = ab + HSTAGE * 4;
        cp16(bb,      Wg + s * 32);
        cp16(bb + 16, Wg + s * 32 + 8);
        cp_commit();
    }

    for (int it = 0; it < NIT; it++) {
        cp_wait<1>();
        __syncthreads();

        {   // issue stage it+2
            int s = it + 2;
            if (s < NIT) {
                uint32_t ab = sbase + (uint32_t)((s % 3) * 2 * HSTAGE) * 4 + rowOff;
                cp16(ab,      Ag + s * 32);
                cp16(ab + 16, Ag + s * 32 + 8);
                uint32_t bb = ab + HSTAGE * 4;
                cp16(bb,      Wg + s * 32);
                cp16(bb + 16, Wg + s * 32 + 8);
            }
            cp_commit();
        }

        const uint32_t* Ac = smg + (it % 3) * 2 * HSTAGE;
        const uint32_t* Bc = Ac + HSTAGE;
#pragma unroll
        for (int kk = 0; kk < 2; kk++) {
            const int kb = kk * 8;
            uint32_t af[4][4], bf[4][2];
#pragma unroll
            for (int mt = 0; mt < 4; mt++) {
                int r0 = (wr * 64 + mt * 16 + g) * HKS + kb + tq;
                af[mt][0] = Ac[r0];
                af[mt][1] = Ac[r0 + 8 * HKS];
                af[mt][2] = Ac[r0 + 4];
                af[mt][3] = Ac[r0 + 8 * HKS + 4];
            }
#pragma unroll
            for (int nt = 0; nt < 4; nt++) {
                int c0 = (wc * 32 + nt * 8 + g) * HKS + kb + tq;
                bf[nt][0] = Bc[c0];
                bf[nt][1] = Bc[c0 + 4];
            }
#pragma unroll
            for (int mt = 0; mt < 4; mt++)
#pragma unroll
                for (int nt = 0; nt < 4; nt++)
                    mma16(acc[mt][nt], af[mt], bf[nt]);
        }
    }

    // Epilogue: c0,c1 = (row g, cols 2tq,2tq+1); c2,c3 = row g+8. Pairs = RoPE pairs.
    const float oscale = scaleQ ? 0.125f : 1.0f;
#pragma unroll
    for (int mt = 0; mt < 4; mt++) {
#pragma unroll
        for (int hi = 0; hi < 2; hi++) {
            int row = mBase + wr * 64 + mt * 16 + g + hi * 8;
            int p   = doRope ? pos[row & (S - 1)] : 0;
#pragma unroll
            for (int nt = 0; nt < 4; nt++) {
                float c0 = acc[mt][nt][hi * 2 + 0];
                float c1 = acc[mt][nt][hi * 2 + 1];
                int col = nBase + wc * 32 + nt * 8 + tq * 2;
                if (doRope) {
                    int e = col & 63;
                    float freq = powf(10000.0f, -(float)e * (1.0f / 64.0f));
                    float sn, cs;
                    sincosf((float)p * freq, &sn, &cs);
                    float v0 = c0, v1 = c1;
                    c0 = cs * v0 - sn * v1;
                    c1 = sn * v0 + cs * v1;
                }
                if (halfOut) {
                    __half* Ch = (__half*)Cout;
                    *(uint32_t*)&Ch[(size_t)row * D + col] =
                        h2u(__floats2half2_rn(c0 * oscale, c1 * oscale));
                } else {
                    float* Cf = (float*)Cout;
                    *(float2*)&Cf[(size_t)row * D + col] = make_float2(c0, c1);
                }
            }
        }
    }
}

__global__ void __launch_bounds__(256)
qkv_kernel(const int* __restrict__ pos)
{
    int z = blockIdx.z;
    const __half* W = (z == 0) ? g_WQh : (z == 1) ? g_WKh : g_WVh;
    __half* Cd      = (z == 0) ? g_Qh  : (z == 1) ? g_Kh  : g_Vh;
    gemm_h(g_xh, W, Cd, true, pos, z < 2, z == 0);
}

__global__ void __launch_bounds__(256)
oproj_kernel(float* __restrict__ out)
{
    gemm_h(g_ATh, g_WOh, out, false, nullptr, false, false);
}

// ---------------------------------------------------------------------------
// Flash attention, fp16 mma. Block = (b, h, 128-row q tile), 256 thr.
// Q pre-scaled by 1/8. All smem rows stride 36 uints (=4 mod 32): fragment
// half2 loads hit banks 4g+tq — conflict-free. V fragments via ldmatrix.trans.
// ---------------------------------------------------------------------------
static constexpr int AQ_OFF = 0;              // Qs [128][36]
static constexpr int AK_OFF = 128 * 36;       // Ks [64][36]
static constexpr int AV_OFF = AK_OFF + 64 * 36;   // Vs [64][36]
static constexpr int AP_OFF = AV_OFF + 64 * 36;   // Ps [128][36]
static constexpr int ATT_SMEM_BYTES = (AP_OFF + 128 * 36) * 4;   // 55296

__global__ void __launch_bounds__(256)
attn_kernel()
{
    extern __shared__ uint32_t smu[];
    uint32_t* Qs = smu + AQ_OFF;
    uint32_t* Ks = smu + AK_OFF;
    uint32_t* Vs = smu + AV_OFF;
    uint32_t* Ps = smu + AP_OFF;
    const uint32_t vbase = (uint32_t)__cvta_generic_to_shared(smu) + AV_OFF * 4;

    const int t    = threadIdx.x;
    const int lane = t & 31;
    const int w    = t >> 5;
    const int g    = lane >> 2;
    const int tq   = lane & 3;
    const int qt   = gridDim.x - 1 - blockIdx.x;   // big tiles first
    const int h    = blockIdx.y;
    const int b    = blockIdx.z;

    // ---- load Q tile (128 x 64 halves) ----
    {
        const __half* Qg = g_Qh + (size_t)(b * S + qt * 128) * D + h * DK;
        int r  = t >> 1;
        int cb = (t & 1) * 4;          // uint4 chunk base (each = 8 halves)
#pragma unroll
        for (int j = 0; j < 4; j++) {
            int ch = cb + j;
            uint4 v = *(const uint4*)(Qg + (size_t)r * D + ch * 8);
            *(uint4*)&Qs[r * 36 + ch * 4] = v;
        }
    }

    float m0 = -1e30f, m1 = -1e30f, l0 = 0.0f, l1 = 0.0f;
    float oacc[8][4];
#pragma unroll
    for (int dt = 0; dt < 8; dt++)
#pragma unroll
        for (int r = 0; r < 4; r++) oacc[dt][r] = 0.0f;

    const __half* Kg = g_Kh + (size_t)(b * S) * D + h * DK;
    const __half* Vg = g_Vh + (size_t)(b * S) * D + h * DK;

    const int nTiles   = 2 * qt + 2;
    const int rowsBase = qt * 128 + w * 16 + g;

    const int lr  = t >> 2;          // kv row this thread stages
    const int lc0 = (t & 3) * 2;     // uint4 chunk base (2 chunks of 8 halves)

    for (int tt = 0; tt < nTiles; tt++) {
        // hoist KV global loads above barrier
        uint4 kreg[2], vreg[2];
        {
            const __half* Kp = Kg + (size_t)(tt * 64 + lr) * D + lc0 * 8;
            const __half* Vp = Vg + (size_t)(tt * 64 + lr) * D + lc0 * 8;
            kreg[0] = *(const uint4*)(Kp);
            kreg[1] = *(const uint4*)(Kp + 8);
            vreg[0] = *(const uint4*)(Vp);
            vreg[1] = *(const uint4*)(Vp + 8);
        }
        __syncthreads();
        *(uint4*)&Ks[lr * 36 + lc0 * 4]     = kreg[0];
        *(uint4*)&Ks[lr * 36 + lc0 * 4 + 4] = kreg[1];
        *(uint4*)&Vs[lr * 36 + lc0 * 4]     = vreg[0];
        *(uint4*)&Vs[lr * 36 + lc0 * 4 + 4] = vreg[1];
        __syncthreads();

        // ---- S = Q K^T ----
        float sc[8][4];
#pragma unroll
        for (int nt = 0; nt < 8; nt++)
#pragma unroll
            for (int r = 0; r < 4; r++) sc[nt][r] = 0.0f;

#pragma unroll
        for (int kk = 0; kk < 4; kk++) {   // k16 slabs over dk=64
            const int kb = kk * 8;
            uint32_t qf[4];
            int rq = (w * 16 + g) * 36 + kb + tq;
            qf[0] = Qs[rq];
            qf[1] = Qs[rq + 8 * 36];
            qf[2] = Qs[rq + 4];
            qf[3] = Qs[rq + 8 * 36 + 4];
#pragma unroll
            for (int nt = 0; nt < 8; nt++) {
                int c0 = (nt * 8 + g) * 36 + kb + tq;
                uint32_t bf[2] = { Ks[c0], Ks[c0 + 4] };
                mma16(sc[nt], qf, bf);
            }
        }

        // ---- causal mask (last two tiles only) ----
        if (tt >= 2 * qt) {
#pragma unroll
            for (int nt = 0; nt < 8; nt++) {
                int col = tt * 64 + nt * 8 + tq * 2;
                if (col > rowsBase)         sc[nt][0] = -1e30f;
                if (col + 1 > rowsBase)     sc[nt][1] = -1e30f;
                if (col > rowsBase + 8)     sc[nt][2] = -1e30f;
                if (col + 1 > rowsBase + 8) sc[nt][3] = -1e30f;
            }
        }

        // ---- online softmax (rows g, g+8; reduce over 4 lanes of group) ----
        float mx0 = -1e30f, mx1 = -1e30f;
#pragma unroll
        for (int nt = 0; nt < 8; nt++) {
            mx0 = fmaxf(mx0, fmaxf(sc[nt][0], sc[nt][1]));
            mx1 = fmaxf(mx1, fmaxf(sc[nt][2], sc[nt][3]));
        }
#pragma unroll
        for (int off = 1; off <= 2; off <<= 1) {
            mx0 = fmaxf(mx0, __shfl_xor_sync(0xffffffffu, mx0, off));
            mx1 = fmaxf(mx1, __shfl_xor_sync(0xffffffffu, mx1, off));
        }
        float mn0 = fmaxf(m0, mx0), mn1 = fmaxf(m1, mx1);
        float a0 = __expf(m0 - mn0), a1 = __expf(m1 - mn1);
        float rs0 = 0.0f, rs1 = 0.0f;
        int prow = (w * 16 + g) * 36;
#pragma unroll
        for (int nt = 0; nt < 8; nt++) {
            float p0 = __expf(sc[nt][0] - mn0);
            float p1 = __expf(sc[nt][1] - mn0);
            float p2 = __expf(sc[nt][2] - mn1);
            float p3 = __expf(sc[nt][3] - mn1);
            rs0 += p0 + p1;
            rs1 += p2 + p3;
            Ps[prow + nt * 4 + tq]          = h2u(__floats2half2_rn(p0, p1));
            Ps[prow + 8 * 36 + nt * 4 + tq] = h2u(__floats2half2_rn(p2, p3));
        }
#pragma unroll
        for (int off = 1; off <= 2; off <<= 1) {
            rs0 += __shfl_xor_sync(0xffffffffu, rs0, off);
            rs1 += __shfl_xor_sync(0xffffffffu, rs1, off);
        }
        l0 = l0 * a0 + rs0;  m0 = mn0;
        l1 = l1 * a1 + rs1;  m1 = mn1;
#pragma unroll
        for (int dt = 0; dt < 8; dt++) {
            oacc[dt][0] *= a0;  oacc[dt][1] *= a0;
            oacc[dt][2] *= a1;  oacc[dt][3] *= a1;
        }
        __syncwarp();

        // ---- O += P V  (V fragments via ldmatrix.x4.trans) ----
#pragma unroll
        for (int kk = 0; kk < 4; kk++) {   // k16 slabs over kv=64
            const int kb = kk * 8;
            uint32_t pf[4];
            int rp = (w * 16 + g) * 36 + kb + tq;
            pf[0] = Ps[rp];
            pf[1] = Ps[rp + 8 * 36];
            pf[2] = Ps[rp + 4];
            pf[3] = Ps[rp + 8 * 36 + 4];
#pragma unroll
            for (int dt2 = 0; dt2 < 4; dt2++) {   // pairs of d8 tiles
                // lane groups: 0-7 -> (k rows +0..7, tile 2dt2), 8-15 -> +8 rows,
                // 16-23 -> tile 2dt2+1, 24-31 -> +8 rows tile 2dt2+1
                int lrow = kk * 16 + (lane & 7) + ((lane >> 3) & 1) * 8;
                int lcol = dt2 * 32 + ((lane >> 4) & 1) * 16;   // bytes
                uint32_t addr = vbase + (uint32_t)(lrow * 144 + lcol);
                uint32_t v0, v1, v2, v3;
                ldsm_x4_trans(v0, v1, v2, v3, addr);
                uint32_t bA[2] = { v0, v1 };
                uint32_t bB[2] = { v2, v3 };
                mma16(oacc[dt2 * 2 + 0], pf, bA);
                mma16(oacc[dt2 * 2 + 1], pf, bB);
            }
        }
        __syncwarp();
    }

    // ---- epilogue: normalize, store half to g_ATh ----
    float inv0 = 1.0f / l0, inv1 = 1.0f / l1;
    __half* Og = g_ATh + (size_t)(b * S + qt * 128 + w * 16 + g) * D + h * DK;
#pragma unroll
    for (int dt = 0; dt < 8; dt++) {
        int cc = dt * 8 + tq * 2;
        *(uint32_t*)(Og + cc) =
            h2u(__floats2half2_rn(oacc[dt][0] * inv0, oacc[dt][1] * inv0));
        *(uint32_t*)(Og + 8 * (size_t)D + cc) =
            h2u(__floats2half2_rn(oacc[dt][2] * inv1, oacc[dt][3] * inv1));
    }
}

// ---------------------------------------------------------------------------
extern "C" void kernel_launch(void* const* d_in, const int* in_sizes, int n_in,
                              void* d_out, int out_size)
{
    const float* x   = (const float*)d_in[0];
    const int*   pos = (const int*)  d_in[1];
    const float* WQ  = (const float*)d_in[2];
    const float* WK  = (const float*)d_in[3];
    const float* WV  = (const float*)d_in[4];
    const float* WO  = (const float*)d_in[5];
    float* out = (float*)d_out;

    __half* xh;
    cudaGetSymbolAddress((void**)&xh, g_xh);

    tohalf_kernel<<<(M * D / 4 + 255) / 256, 256>>>(x, xh, M * D / 4);
    tohalfW_kernel<<<dim3(D * D / 4 / 256, 4, 1), 256>>>(WQ, WK, WV, WO);

    cudaFuncSetAttribute(qkv_kernel,
                         cudaFuncAttributeMaxDynamicSharedMemorySize,
                         GEMM_SMEM_BYTES);
    cudaFuncSetAttribute(oproj_kernel,
                         cudaFuncAttributeMaxDynamicSharedMemorySize,
                         GEMM_SMEM_BYTES);
    cudaFuncSetAttribute(attn_kernel,
                         cudaFuncAttributeMaxDynamicSharedMemorySize,
                         ATT_SMEM_BYTES);

    qkv_kernel<<<dim3(D / 128, M / 128, 3), 256, GEMM_SMEM_BYTES>>>(pos);
    attn_kernel<<<dim3(S / 128, NH, B), 256, ATT_SMEM_BYTES>>>();
    oproj_kernel<<<dim3(D / 128, M / 128, 1), 256, GEMM_SMEM_BYTES>>>(out);
}

// round 13
// speedup vs baseline: 5.4853x; 1.0463x over previous
#include <cuda_runtime.h>
#include <cuda_fp16.h>
#include <cstdint>

static constexpr int B  = 2;
static constexpr int S  = 2048;
static constexpr int D  = 1024;
static constexpr int NH = 16;
static constexpr int DK = 64;
static constexpr int M  = B * S;   // 4096

// Scratch (allocation-free rule: __device__ globals) — all fp16
__device__ __half g_Qh [M * D];
__device__ __half g_Kh [M * D];
__device__ __half g_Vh [M * D];
__device__ __half g_ATh[M * D];
__device__ __half g_xh [M * D];
__device__ __half g_WQh[D * D];
__device__ __half g_WKh[D * D];
__device__ __half g_WVh[D * D];
__device__ __half g_WOh[D * D];

// ---------------------------------------------------------------------------
// helpers
// ---------------------------------------------------------------------------
__device__ __forceinline__ void mma16(float* c, const uint32_t* a, const uint32_t* b) {
    asm volatile(
        "mma.sync.aligned.m16n8k16.row.col.f32.f16.f16.f32 "
        "{%0,%1,%2,%3}, {%4,%5,%6,%7}, {%8,%9}, {%0,%1,%2,%3};"
        : "+f"(c[0]), "+f"(c[1]), "+f"(c[2]), "+f"(c[3])
        : "r"(a[0]), "r"(a[1]), "r"(a[2]), "r"(a[3]), "r"(b[0]), "r"(b[1]));
}

__device__ __forceinline__ void ldsm_x4_trans(uint32_t& r0, uint32_t& r1,
                                              uint32_t& r2, uint32_t& r3,
                                              uint32_t addr) {
    asm volatile(
        "ldmatrix.sync.aligned.m8n8.x4.trans.shared.b16 {%0,%1,%2,%3}, [%4];"
        : "=r"(r0), "=r"(r1), "=r"(r2), "=r"(r3) : "r"(addr));
}

__device__ __forceinline__ void cp16(uint32_t smem_dst, const void* gsrc) {
    asm volatile("cp.async.cg.shared.global [%0], [%1], 16;"
                 :: "r"(smem_dst), "l"(gsrc));
}
__device__ __forceinline__ void cp_commit() {
    asm volatile("cp.async.commit_group;" ::: "memory");
}
template <int N>
__device__ __forceinline__ void cp_wait() {
    asm volatile("cp.async.wait_group %0;" :: "n"(N) : "memory");
}

__device__ __forceinline__ uint32_t h2u(__half2 h) {
    return *reinterpret_cast<uint32_t*>(&h);
}

// ---------------------------------------------------------------------------
// fp32 -> fp16 input conversion
// ---------------------------------------------------------------------------
__global__ void __launch_bounds__(256)
tohalf_kernel(const float* __restrict__ src, __half* __restrict__ dst, int n4)
{
    int i = blockIdx.x * 256 + threadIdx.x;
    if (i < n4) {
        float4 v = ((const float4*)src)[i];
        uint2 o;
        o.x = h2u(__floats2half2_rn(v.x, v.y));
        o.y = h2u(__floats2half2_rn(v.z, v.w));
        ((uint2*)dst)[i] = o;
    }
}

__global__ void __launch_bounds__(256)
tohalfW_kernel(const float* __restrict__ WQ, const float* __restrict__ WK,
               const float* __restrict__ WV, const float* __restrict__ WO)
{
    int z = blockIdx.y;
    const float* s = (z == 0) ? WQ : (z == 1) ? WK : (z == 2) ? WV : WO;
    __half*      d = (z == 0) ? g_WQh : (z == 1) ? g_WKh : (z == 2) ? g_WVh : g_WOh;
    int i = blockIdx.x * 256 + threadIdx.x;
    float4 v = ((const float4*)s)[i];
    uint2 o;
    o.x = h2u(__floats2half2_rn(v.x, v.y));
    o.y = h2u(__floats2half2_rn(v.z, v.w));
    ((uint2*)d)[i] = o;
}

// ---------------------------------------------------------------------------
// fp16 GEMM: C[m][n] = sum_k A[m][k] * W[n][k]
// 128x128 tile, BK=32 halves, 256 threads = 8 warps (2x4, each 64m x 32n).
// 3-stage cp.async pipeline; smem rows 40 halves -> conflict-free fragments.
// scaleQ folds 1/8 * log2(e) so attention can use exp2.
// ---------------------------------------------------------------------------
static constexpr int HKS    = 20;           // uints per row
static constexpr int HSTAGE = 128 * HKS;    // uints per matrix per stage
static constexpr int GEMM_SMEM_BYTES = 3 * 2 * HSTAGE * 4;   // 61440

static constexpr float QSCALE = 0.125f * 1.44269504088896f;

__device__ __forceinline__ void gemm_h(const __half* __restrict__ A,
                                       const __half* __restrict__ W,
                                       void* __restrict__ Cout, bool halfOut,
                                       const int* __restrict__ pos,
                                       bool doRope, bool scaleQ)
{
    extern __shared__ uint32_t smg[];
    const uint32_t sbase = (uint32_t)__cvta_generic_to_shared(smg);

    const int t    = threadIdx.x;
    const int lane = t & 31;
    const int w    = t >> 5;
    const int g    = lane >> 2;
    const int tq   = lane & 3;
    const int wr   = w >> 2;
    const int wc   = w & 3;
    const int mBase = blockIdx.y * 128;
    const int nBase = blockIdx.x * 128;

    const int srow = t >> 1;
    const int sc0  = (t & 1) * 2;
    const __half* Ag = A + (size_t)(mBase + srow) * D + sc0 * 8;
    const __half* Wg = W + (size_t)(nBase + srow) * D + sc0 * 8;
    const uint32_t rowOff = (uint32_t)(srow * HKS * 4 + sc0 * 16);

    float acc[4][4][4];
#pragma unroll
    for (int i = 0; i < 4; i++)
#pragma unroll
        for (int j = 0; j < 4; j++)
#pragma unroll
            for (int r = 0; r < 4; r++) acc[i][j][r] = 0.0f;

    const int NIT = D / 32;

#pragma unroll
    for (int s = 0; s < 2; s++) {
        uint32_t ab = sbase + (uint32_t)(s * 2 * HSTAGE) * 4 + rowOff;
        cp16(ab,      Ag + s * 32);
        cp16(ab + 16, Ag + s * 32 + 8);
        uint32_t bb = ab + HSTAGE * 4;
        cp16(bb,      Wg + s * 32);
        cp16(bb + 16, Wg + s * 32 + 8);
        cp_commit();
    }

    for (int it = 0; it < NIT; it++) {
        cp_wait<1>();
        __syncthreads();

        {
            int s = it + 2;
            if (s < NIT) {
                uint32_t ab = sbase + (uint32_t)((s % 3) * 2 * HSTAGE) * 4 + rowOff;
                cp16(ab,      Ag + s * 32);
                cp16(ab + 16, Ag + s * 32 + 8);
                uint32_t bb = ab + HSTAGE * 4;
                cp16(bb,      Wg + s * 32);
                cp16(bb + 16, Wg + s * 32 + 8);
            }
            cp_commit();
        }

        const uint32_t* Ac = smg + (it % 3) * 2 * HSTAGE;
        const uint32_t* Bc = Ac + HSTAGE;
#pragma unroll
        for (int kk = 0; kk < 2; kk++) {
            const int kb = kk * 8;
            uint32_t af[4][4], bf[4][2];
#pragma unroll
            for (int mt = 0; mt < 4; mt++) {
                int r0 = (wr * 64 + mt * 16 + g) * HKS + kb + tq;
                af[mt][0] = Ac[r0];
                af[mt][1] = Ac[r0 + 8 * HKS];
                af[mt][2] = Ac[r0 + 4];
                af[mt][3] = Ac[r0 + 8 * HKS + 4];
            }
#pragma unroll
            for (int nt = 0; nt < 4; nt++) {
                int c0 = (wc * 32 + nt * 8 + g) * HKS + kb + tq;
                bf[nt][0] = Bc[c0];
                bf[nt][1] = Bc[c0 + 4];
            }
#pragma unroll
            for (int mt = 0; mt < 4; mt++)
#pragma unroll
                for (int nt = 0; nt < 4; nt++)
                    mma16(acc[mt][nt], af[mt], bf[nt]);
        }
    }

    const float oscale = scaleQ ? QSCALE : 1.0f;
#pragma unroll
    for (int mt = 0; mt < 4; mt++) {
#pragma unroll
        for (int hi = 0; hi < 2; hi++) {
            int row = mBase + wr * 64 + mt * 16 + g + hi * 8;
            int p   = doRope ? pos[row & (S - 1)] : 0;
#pragma unroll
            for (int nt = 0; nt < 4; nt++) {
                float c0 = acc[mt][nt][hi * 2 + 0];
                float c1 = acc[mt][nt][hi * 2 + 1];
                int col = nBase + wc * 32 + nt * 8 + tq * 2;
                if (doRope) {
                    int e = col & 63;
                    float freq = powf(10000.0f, -(float)e * (1.0f / 64.0f));
                    float sn, cs;
                    sincosf((float)p * freq, &sn, &cs);
                    float v0 = c0, v1 = c1;
                    c0 = cs * v0 - sn * v1;
                    c1 = sn * v0 + cs * v1;
                }
                if (halfOut) {
                    __half* Ch = (__half*)Cout;
                    *(uint32_t*)&Ch[(size_t)row * D + col] =
                        h2u(__floats2half2_rn(c0 * oscale, c1 * oscale));
                } else {
                    float* Cf = (float*)Cout;
                    *(float2*)&Cf[(size_t)row * D + col] = make_float2(c0, c1);
                }
            }
        }
    }
}

__global__ void __launch_bounds__(256)
qkv_kernel(const int* __restrict__ pos)
{
    int z = blockIdx.z;
    const __half* W = (z == 0) ? g_WQh : (z == 1) ? g_WKh : g_WVh;
    __half* Cd      = (z == 0) ? g_Qh  : (z == 1) ? g_Kh  : g_Vh;
    gemm_h(g_xh, W, Cd, true, pos, z < 2, z == 0);
}

__global__ void __launch_bounds__(256)
oproj_kernel(float* __restrict__ out)
{
    gemm_h(g_ATh, g_WOh, out, false, nullptr, false, false);
}

// ---------------------------------------------------------------------------
// Flash attention, fp16 mma, P kept entirely in registers (QK C-fragment ==
// PV A-fragment layout). Scores arrive in log2 domain (Q pre-scaled by
// 0.125*log2e) -> exp2f. smem: Q/K/V only, rows stride 36 uints.
// ---------------------------------------------------------------------------
static constexpr int AQ_OFF = 0;                  // Qs [128][36]
static constexpr int AK_OFF = 128 * 36;           // Ks [64][36]
static constexpr int AV_OFF = AK_OFF + 64 * 36;   // Vs [64][36]
static constexpr int ATT_SMEM_BYTES = (AV_OFF + 64 * 36) * 4;   // 36864

__global__ void __launch_bounds__(256, 2)
attn_kernel()
{
    extern __shared__ uint32_t smu[];
    uint32_t* Qs = smu + AQ_OFF;
    uint32_t* Ks = smu + AK_OFF;
    uint32_t* Vs = smu + AV_OFF;
    const uint32_t vbase = (uint32_t)__cvta_generic_to_shared(smu) + AV_OFF * 4;

    const int t    = threadIdx.x;
    const int lane = t & 31;
    const int w    = t >> 5;
    const int g    = lane >> 2;
    const int tq   = lane & 3;
    const int qt   = gridDim.x - 1 - blockIdx.x;   // big tiles first
    const int h    = blockIdx.y;
    const int b    = blockIdx.z;

    // ---- load Q tile (128 x 64 halves, already scaled by 1/8*log2e) ----
    {
        const __half* Qg = g_Qh + (size_t)(b * S + qt * 128) * D + h * DK;
        int r  = t >> 1;
        int cb = (t & 1) * 4;
#pragma unroll
        for (int j = 0; j < 4; j++) {
            int ch = cb + j;
            uint4 v = *(const uint4*)(Qg + (size_t)r * D + ch * 8);
            *(uint4*)&Qs[r * 36 + ch * 4] = v;
        }
    }

    float m0 = -1e30f, m1 = -1e30f, l0 = 0.0f, l1 = 0.0f;
    float oacc[8][4];
#pragma unroll
    for (int dt = 0; dt < 8; dt++)
#pragma unroll
        for (int r = 0; r < 4; r++) oacc[dt][r] = 0.0f;

    const __half* Kg = g_Kh + (size_t)(b * S) * D + h * DK;
    const __half* Vg = g_Vh + (size_t)(b * S) * D + h * DK;

    const int nTiles   = 2 * qt + 2;
    const int rowsBase = qt * 128 + w * 16 + g;

    const int lr  = t >> 2;
    const int lc0 = (t & 3) * 2;

    for (int tt = 0; tt < nTiles; tt++) {
        // hoist KV global loads above barrier
        uint4 kreg[2], vreg[2];
        {
            const __half* Kp = Kg + (size_t)(tt * 64 + lr) * D + lc0 * 8;
            const __half* Vp = Vg + (size_t)(tt * 64 + lr) * D + lc0 * 8;
            kreg[0] = *(const uint4*)(Kp);
            kreg[1] = *(const uint4*)(Kp + 8);
            vreg[0] = *(const uint4*)(Vp);
            vreg[1] = *(const uint4*)(Vp + 8);
        }
        __syncthreads();
        *(uint4*)&Ks[lr * 36 + lc0 * 4]     = kreg[0];
        *(uint4*)&Ks[lr * 36 + lc0 * 4 + 4] = kreg[1];
        *(uint4*)&Vs[lr * 36 + lc0 * 4]     = vreg[0];
        *(uint4*)&Vs[lr * 36 + lc0 * 4 + 4] = vreg[1];
        __syncthreads();

        // ---- S = Q K^T  (log2 domain) ----
        float sc[8][4];
#pragma unroll
        for (int nt = 0; nt < 8; nt++)
#pragma unroll
            for (int r = 0; r < 4; r++) sc[nt][r] = 0.0f;

#pragma unroll
        for (int kk = 0; kk < 4; kk++) {
            const int kb = kk * 8;
            uint32_t qf[4];
            int rq = (w * 16 + g) * 36 + kb + tq;
            qf[0] = Qs[rq];
            qf[1] = Qs[rq + 8 * 36];
            qf[2] = Qs[rq + 4];
            qf[3] = Qs[rq + 8 * 36 + 4];
#pragma unroll
            for (int nt = 0; nt < 8; nt++) {
                int c0 = (nt * 8 + g) * 36 + kb + tq;
                uint32_t bf[2] = { Ks[c0], Ks[c0 + 4] };
                mma16(sc[nt], qf, bf);
            }
        }

        // ---- causal mask (last two tiles only) ----
        if (tt >= 2 * qt) {
#pragma unroll
            for (int nt = 0; nt < 8; nt++) {
                int col = tt * 64 + nt * 8 + tq * 2;
                if (col > rowsBase)         sc[nt][0] = -1e30f;
                if (col + 1 > rowsBase)     sc[nt][1] = -1e30f;
                if (col > rowsBase + 8)     sc[nt][2] = -1e30f;
                if (col + 1 > rowsBase + 8) sc[nt][3] = -1e30f;
            }
        }

        // ---- online softmax (exp2; rows g, g+8; reduce over 4 lanes) ----
        float mx0 = -1e30f, mx1 = -1e30f;
#pragma unroll
        for (int nt = 0; nt < 8; nt++) {
            mx0 = fmaxf(mx0, fmaxf(sc[nt][0], sc[nt][1]));
            mx1 = fmaxf(mx1, fmaxf(sc[nt][2], sc[nt][3]));
        }
#pragma unroll
        for (int off = 1; off <= 2; off <<= 1) {
            mx0 = fmaxf(mx0, __shfl_xor_sync(0xffffffffu, mx0, off));
            mx1 = fmaxf(mx1, __shfl_xor_sync(0xffffffffu, mx1, off));
        }
        float mn0 = fmaxf(m0, mx0), mn1 = fmaxf(m1, mx1);
        float a0 = exp2f(m0 - mn0), a1 = exp2f(m1 - mn1);
        float rs0 = 0.0f, rs1 = 0.0f;
        uint32_t ph[8][2];   // P in PV A-fragment layout — no smem round trip
#pragma unroll
        for (int nt = 0; nt < 8; nt++) {
            float p0 = exp2f(sc[nt][0] - mn0);
            float p1 = exp2f(sc[nt][1] - mn0);
            float p2 = exp2f(sc[nt][2] - mn1);
            float p3 = exp2f(sc[nt][3] - mn1);
            rs0 += p0 + p1;
            rs1 += p2 + p3;
            ph[nt][0] = h2u(__floats2half2_rn(p0, p1));
            ph[nt][1] = h2u(__floats2half2_rn(p2, p3));
        }
#pragma unroll
        for (int off = 1; off <= 2; off <<= 1) {
            rs0 += __shfl_xor_sync(0xffffffffu, rs0, off);
            rs1 += __shfl_xor_sync(0xffffffffu, rs1, off);
        }
        l0 = l0 * a0 + rs0;  m0 = mn0;
        l1 = l1 * a1 + rs1;  m1 = mn1;
#pragma unroll
        for (int dt = 0; dt < 8; dt++) {
            oacc[dt][0] *= a0;  oacc[dt][1] *= a0;
            oacc[dt][2] *= a1;  oacc[dt][3] *= a1;
        }

        // ---- O += P V  (P from regs; V fragments via ldmatrix.x4.trans) ----
#pragma unroll
        for (int kk = 0; kk < 4; kk++) {
            uint32_t pf[4] = { ph[2 * kk][0], ph[2 * kk][1],
                               ph[2 * kk + 1][0], ph[2 * kk + 1][1] };
#pragma unroll
            for (int dt2 = 0; dt2 < 4; dt2++) {
                int lrow = kk * 16 + (lane & 7) + ((lane >> 3) & 1) * 8;
                int lcol = dt2 * 32 + ((lane >> 4) & 1) * 16;   // bytes
                uint32_t addr = vbase + (uint32_t)(lrow * 144 + lcol);
                uint32_t v0, v1, v2, v3;
                ldsm_x4_trans(v0, v1, v2, v3, addr);
                uint32_t bA[2] = { v0, v1 };
                uint32_t bB[2] = { v2, v3 };
                mma16(oacc[dt2 * 2 + 0], pf, bA);
                mma16(oacc[dt2 * 2 + 1], pf, bB);
            }
        }
    }

    // ---- epilogue: normalize, store half to g_ATh ----
    float inv0 = 1.0f / l0, inv1 = 1.0f / l1;
    __half* Og = g_ATh + (size_t)(b * S + qt * 128 + w * 16 + g) * D + h * DK;
#pragma unroll
    for (int dt = 0; dt < 8; dt++) {
        int cc = dt * 8 + tq * 2;
        *(uint32_t*)(Og + cc) =
            h2u(__floats2half2_rn(oacc[dt][0] * inv0, oacc[dt][1] * inv0));
        *(uint32_t*)(Og + 8 * (size_t)D + cc) =
            h2u(__floats2half2_rn(oacc[dt][2] * inv1, oacc[dt][3] * inv1));
    }
}

// ---------------------------------------------------------------------------
extern "C" void kernel_launch(void* const* d_in, const int* in_sizes, int n_in,
                              void* d_out, int out_size)
{
    const float* x   = (const float*)d_in[0];
    const int*   pos = (const int*)  d_in[1];
    const float* WQ  = (const float*)d_in[2];
    const float* WK  = (const float*)d_in[3];
    const float* WV  = (const float*)d_in[4];
    const float* WO  = (const float*)d_in[5];
    float* out = (float*)d_out;

    __half* xh;
    cudaGetSymbolAddress((void**)&xh, g_xh);

    tohalf_kernel<<<(M * D / 4 + 255) / 256, 256>>>(x, xh, M * D / 4);
    tohalfW_kernel<<<dim3(D * D / 4 / 256, 4, 1), 256>>>(WQ, WK, WV, WO);

    cudaFuncSetAttribute(qkv_kernel,
                         cudaFuncAttributeMaxDynamicSharedMemorySize,
                         GEMM_SMEM_BYTES);
    cudaFuncSetAttribute(oproj_kernel,
                         cudaFuncAttributeMaxDynamicSharedMemorySize,
                         GEMM_SMEM_BYTES);
    cudaFuncSetAttribute(attn_kernel,
                         cudaFuncAttributeMaxDynamicSharedMemorySize,
                         ATT_SMEM_BYTES);

    qkv_kernel<<<dim3(D / 128, M / 128, 3), 256, GEMM_SMEM_BYTES>>>(pos);
    attn_kernel<<<dim3(S / 128, NH, B), 256, ATT_SMEM_BYTES>>>();
    oproj_kernel<<<dim3(D / 128, M / 128, 1), 256, GEMM_SMEM_BYTES>>>(out);
}

// round 14
// speedup vs baseline: 5.9559x; 1.0858x over previous
#include <cuda_runtime.h>
#include <cuda_fp16.h>
#include <cstdint>

static constexpr int B  = 2;
static constexpr int S  = 2048;
static constexpr int D  = 1024;
static constexpr int NH = 16;
static constexpr int DK = 64;
static constexpr int M  = B * S;   // 4096

// Scratch (allocation-free rule: __device__ globals) — all fp16
__device__ __half g_Qh [M * D];
__device__ __half g_Kh [M * D];
__device__ __half g_Vh [M * D];
__device__ __half g_ATh[M * D];
__device__ __half g_xh [M * D];
__device__ __half g_WQh[D * D];
__device__ __half g_WKh[D * D];
__device__ __half g_WVh[D * D];
__device__ __half g_WOh[D * D];

// ---------------------------------------------------------------------------
// helpers
// ---------------------------------------------------------------------------
__device__ __forceinline__ void mma16(float* c, const uint32_t* a, const uint32_t* b) {
    asm volatile(
        "mma.sync.aligned.m16n8k16.row.col.f32.f16.f16.f32 "
        "{%0,%1,%2,%3}, {%4,%5,%6,%7}, {%8,%9}, {%0,%1,%2,%3};"
        : "+f"(c[0]), "+f"(c[1]), "+f"(c[2]), "+f"(c[3])
        : "r"(a[0]), "r"(a[1]), "r"(a[2]), "r"(a[3]), "r"(b[0]), "r"(b[1]));
}

__device__ __forceinline__ void ldsm_x4(uint32_t& r0, uint32_t& r1,
                                        uint32_t& r2, uint32_t& r3,
                                        uint32_t addr) {
    asm volatile(
        "ldmatrix.sync.aligned.m8n8.x4.shared.b16 {%0,%1,%2,%3}, [%4];"
        : "=r"(r0), "=r"(r1), "=r"(r2), "=r"(r3) : "r"(addr));
}

__device__ __forceinline__ void ldsm_x4_trans(uint32_t& r0, uint32_t& r1,
                                              uint32_t& r2, uint32_t& r3,
                                              uint32_t addr) {
    asm volatile(
        "ldmatrix.sync.aligned.m8n8.x4.trans.shared.b16 {%0,%1,%2,%3}, [%4];"
        : "=r"(r0), "=r"(r1), "=r"(r2), "=r"(r3) : "r"(addr));
}

__device__ __forceinline__ void cp16(uint32_t smem_dst, const void* gsrc) {
    asm volatile("cp.async.cg.shared.global [%0], [%1], 16;"
                 :: "r"(smem_dst), "l"(gsrc));
}
__device__ __forceinline__ void cp_commit() {
    asm volatile("cp.async.commit_group;" ::: "memory");
}
template <int N>
__device__ __forceinline__ void cp_wait() {
    asm volatile("cp.async.wait_group %0;" :: "n"(N) : "memory");
}

__device__ __forceinline__ uint32_t h2u(__half2 h) {
    return *reinterpret_cast<uint32_t*>(&h);
}

// ---------------------------------------------------------------------------
// fp32 -> fp16 input conversion
// ---------------------------------------------------------------------------
__global__ void __launch_bounds__(256)
tohalf_kernel(const float* __restrict__ src, __half* __restrict__ dst, int n4)
{
    int i = blockIdx.x * 256 + threadIdx.x;
    if (i < n4) {
        float4 v = ((const float4*)src)[i];
        uint2 o;
        o.x = h2u(__floats2half2_rn(v.x, v.y));
        o.y = h2u(__floats2half2_rn(v.z, v.w));
        ((uint2*)dst)[i] = o;
    }
}

__global__ void __launch_bounds__(256)
tohalfW_kernel(const float* __restrict__ WQ, const float* __restrict__ WK,
               const float* __restrict__ WV, const float* __restrict__ WO)
{
    int z = blockIdx.y;
    const float* s = (z == 0) ? WQ : (z == 1) ? WK : (z == 2) ? WV : WO;
    __half*      d = (z == 0) ? g_WQh : (z == 1) ? g_WKh : (z == 2) ? g_WVh : g_WOh;
    int i = blockIdx.x * 256 + threadIdx.x;
    float4 v = ((const float4*)s)[i];
    uint2 o;
    o.x = h2u(__floats2half2_rn(v.x, v.y));
    o.y = h2u(__floats2half2_rn(v.z, v.w));
    ((uint2*)d)[i] = o;
}

// ---------------------------------------------------------------------------
// fp16 GEMM: C[m][n] = sum_k A[m][k] * W[n][k]
// 128x128 tile, BK=32 halves, 256 threads = 8 warps (2x4, each 64m x 32n).
// 3-stage cp.async pipeline; fragments via ldmatrix (rows 80B apart ->
// ldsm phases conflict-free). scaleQ folds 1/8*log2(e).
// ---------------------------------------------------------------------------
static constexpr int HKS    = 20;           // uints per row (80 B)
static constexpr int HSTAGE = 128 * HKS;    // uints per matrix per stage
static constexpr int GEMM_SMEM_BYTES = 3 * 2 * HSTAGE * 4;   // 61440

static constexpr float QSCALE = 0.125f * 1.44269504088896f;

__device__ __forceinline__ void gemm_h(const __half* __restrict__ A,
                                       const __half* __restrict__ W,
                                       void* __restrict__ Cout, bool halfOut,
                                       const int* __restrict__ pos,
                                       bool doRope, bool scaleQ)
{
    extern __shared__ uint32_t smg[];
    const uint32_t sbase = (uint32_t)__cvta_generic_to_shared(smg);

    const int t    = threadIdx.x;
    const int lane = t & 31;
    const int w    = t >> 5;
    const int g    = lane >> 2;
    const int tq   = lane & 3;
    const int wr   = w >> 2;
    const int wc   = w & 3;
    const int mBase = blockIdx.y * 128;
    const int nBase = blockIdx.x * 128;

    const int srow = t >> 1;
    const int sc0  = (t & 1) * 2;
    const __half* Ag = A + (size_t)(mBase + srow) * D + sc0 * 8;
    const __half* Wg = W + (size_t)(nBase + srow) * D + sc0 * 8;
    const uint32_t rowOff = (uint32_t)(srow * HKS * 4 + sc0 * 16);

    // ldmatrix per-lane byte offsets (within a stage)
    // A x4: [m-lo,k-lo],[m-hi,k-lo],[m-lo,k-hi],[m-hi,k-hi]
    const uint32_t aRow = (uint32_t)((wr * 64 + ((lane >> 3) & 1) * 8 + (lane & 7)) * 80
                                     + ((lane >> 4) & 1) * 16);
    // B x4: [nt-lo,k-lo],[nt-lo,k-hi],[nt-hi,k-lo],[nt-hi,k-hi]
    const uint32_t bRow = (uint32_t)((wc * 32 + ((lane >> 4) & 1) * 8 + (lane & 7)) * 80
                                     + ((lane >> 3) & 1) * 16);

    float acc[4][4][4];
#pragma unroll
    for (int i = 0; i < 4; i++)
#pragma unroll
        for (int j = 0; j < 4; j++)
#pragma unroll
            for (int r = 0; r < 4; r++) acc[i][j][r] = 0.0f;

    const int NIT = D / 32;

#pragma unroll
    for (int s = 0; s < 2; s++) {
        uint32_t ab = sbase + (uint32_t)(s * 2 * HSTAGE) * 4 + rowOff;
        cp16(ab,      Ag + s * 32);
        cp16(ab + 16, Ag + s * 32 + 8);
        uint32_t bb = ab + HSTAGE * 4;
        cp16(bb,      Wg + s * 32);
        cp16(bb + 16, Wg + s * 32 + 8);
        cp_commit();
    }

    for (int it = 0; it < NIT; it++) {
        cp_wait<1>();
        __syncthreads();

        {
            int s = it + 2;
            if (s < NIT) {
                uint32_t ab = sbase + (uint32_t)((s % 3) * 2 * HSTAGE) * 4 + rowOff;
                cp16(ab,      Ag + s * 32);
                cp16(ab + 16, Ag + s * 32 + 8);
                uint32_t bb = ab + HSTAGE * 4;
                cp16(bb,      Wg + s * 32);
                cp16(bb + 16, Wg + s * 32 + 8);
            }
            cp_commit();
        }

        const uint32_t stA = sbase + (uint32_t)((it % 3) * 2 * HSTAGE) * 4;
        const uint32_t stB = stA + HSTAGE * 4;
#pragma unroll
        for (int kk = 0; kk < 2; kk++) {
            const uint32_t kbB = (uint32_t)(kk * 32);   // bytes
            uint32_t af[4][4], bf[4][2];
#pragma unroll
            for (int mt = 0; mt < 4; mt++)
                ldsm_x4(af[mt][0], af[mt][1], af[mt][2], af[mt][3],
                        stA + aRow + (uint32_t)(mt * 16 * 80) + kbB);
#pragma unroll
            for (int np = 0; np < 2; np++)
                ldsm_x4(bf[np * 2][0], bf[np * 2][1], bf[np * 2 + 1][0],
                        bf[np * 2 + 1][1],
                        stB + bRow + (uint32_t)(np * 16 * 80) + kbB);
#pragma unroll
            for (int mt = 0; mt < 4; mt++)
#pragma unroll
                for (int nt = 0; nt < 4; nt++)
                    mma16(acc[mt][nt], af[mt], bf[nt]);
        }
    }

    const float oscale = scaleQ ? QSCALE : 1.0f;
#pragma unroll
    for (int mt = 0; mt < 4; mt++) {
#pragma unroll
        for (int hi = 0; hi < 2; hi++) {
            int row = mBase + wr * 64 + mt * 16 + g + hi * 8;
            int p   = doRope ? pos[row & (S - 1)] : 0;
#pragma unroll
            for (int nt = 0; nt < 4; nt++) {
                float c0 = acc[mt][nt][hi * 2 + 0];
                float c1 = acc[mt][nt][hi * 2 + 1];
                int col = nBase + wc * 32 + nt * 8 + tq * 2;
                if (doRope) {
                    int e = col & 63;
                    float freq = powf(10000.0f, -(float)e * (1.0f / 64.0f));
                    float sn, cs;
                    sincosf((float)p * freq, &sn, &cs);
                    float v0 = c0, v1 = c1;
                    c0 = cs * v0 - sn * v1;
                    c1 = sn * v0 + cs * v1;
                }
                if (halfOut) {
                    __half* Ch = (__half*)Cout;
                    *(uint32_t*)&Ch[(size_t)row * D + col] =
                        h2u(__floats2half2_rn(c0 * oscale, c1 * oscale));
                } else {
                    float* Cf = (float*)Cout;
                    *(float2*)&Cf[(size_t)row * D + col] = make_float2(c0, c1);
                }
            }
        }
    }
}

__global__ void __launch_bounds__(256)
qkv_kernel(const int* __restrict__ pos)
{
    int z = blockIdx.z;
    const __half* W = (z == 0) ? g_WQh : (z == 1) ? g_WKh : g_WVh;
    __half* Cd      = (z == 0) ? g_Qh  : (z == 1) ? g_Kh  : g_Vh;
    gemm_h(g_xh, W, Cd, true, pos, z < 2, z == 0);
}

__global__ void __launch_bounds__(256)
oproj_kernel(float* __restrict__ out)
{
    gemm_h(g_ATh, g_WOh, out, false, nullptr, false, false);
}

// ---------------------------------------------------------------------------
// Flash attention, fp16 mma. Q fragments hoisted (ldmatrix once), K fragments
// via ldmatrix, P kept in registers, exp2 softmax. smem rows stride 36 uints.
// ---------------------------------------------------------------------------
static constexpr int AQ_OFF = 0;                  // Qs [128][36]
static constexpr int AK_OFF = 128 * 36;           // Ks [64][36]
static constexpr int AV_OFF = AK_OFF + 64 * 36;   // Vs [64][36]
static constexpr int ATT_SMEM_BYTES = (AV_OFF + 64 * 36) * 4;   // 36864

__global__ void __launch_bounds__(256, 2)
attn_kernel()
{
    extern __shared__ uint32_t smu[];
    uint32_t* Qs = smu + AQ_OFF;
    uint32_t* Ks = smu + AK_OFF;
    uint32_t* Vs = smu + AV_OFF;
    const uint32_t sbase = (uint32_t)__cvta_generic_to_shared(smu);
    const uint32_t kbase = sbase + AK_OFF * 4;
    const uint32_t vbase = sbase + AV_OFF * 4;

    const int t    = threadIdx.x;
    const int lane = t & 31;
    const int w    = t >> 5;
    const int g    = lane >> 2;
    const int tq   = lane & 3;
    const int qt   = gridDim.x - 1 - blockIdx.x;   // big tiles first
    const int h    = blockIdx.y;
    const int b    = blockIdx.z;

    // ---- load Q tile (128 x 64 halves, pre-scaled by 1/8*log2e) ----
    {
        const __half* Qg = g_Qh + (size_t)(b * S + qt * 128) * D + h * DK;
        int r  = t >> 1;
        int cb = (t & 1) * 4;
#pragma unroll
        for (int j = 0; j < 4; j++) {
            int ch = cb + j;
            uint4 v = *(const uint4*)(Qg + (size_t)r * D + ch * 8);
            *(uint4*)&Qs[r * 36 + ch * 4] = v;
        }
    }
    __syncthreads();

    // ---- Q fragments: loop-invariant, load once via ldmatrix ----
    uint32_t qfr[4][4];
    {
        const uint32_t qRow = (uint32_t)((w * 16 + ((lane >> 3) & 1) * 8 + (lane & 7)) * 144
                                         + ((lane >> 4) & 1) * 16);
#pragma unroll
        for (int kk = 0; kk < 4; kk++)
            ldsm_x4(qfr[kk][0], qfr[kk][1], qfr[kk][2], qfr[kk][3],
                    sbase + qRow + (uint32_t)(kk * 32));
    }

    float m0 = -1e30f, m1 = -1e30f, l0 = 0.0f, l1 = 0.0f;
    float oacc[8][4];
#pragma unroll
    for (int dt = 0; dt < 8; dt++)
#pragma unroll
        for (int r = 0; r < 4; r++) oacc[dt][r] = 0.0f;

    const __half* Kg = g_Kh + (size_t)(b * S) * D + h * DK;
    const __half* Vg = g_Vh + (size_t)(b * S) * D + h * DK;

    const int nTiles   = 2 * qt + 2;
    const int rowsBase = qt * 128 + w * 16 + g;

    const int lr  = t >> 2;
    const int lc0 = (t & 3) * 2;

    // K ldsm lane offset: [nt-lo,k-lo],[nt-lo,k-hi],[nt-hi,k-lo],[nt-hi,k-hi]
    const uint32_t kRow = (uint32_t)((((lane >> 4) & 1) * 8 + (lane & 7)) * 144
                                     + ((lane >> 3) & 1) * 16);
    // V ldsm.trans lane offset
    const uint32_t vRow = (uint32_t)(((lane & 7) + ((lane >> 3) & 1) * 8) * 144
                                     + ((lane >> 4) & 1) * 16);

    for (int tt = 0; tt < nTiles; tt++) {
        // hoist KV global loads above barrier
        uint4 kreg[2], vreg[2];
        {
            const __half* Kp = Kg + (size_t)(tt * 64 + lr) * D + lc0 * 8;
            const __half* Vp = Vg + (size_t)(tt * 64 + lr) * D + lc0 * 8;
            kreg[0] = *(const uint4*)(Kp);
            kreg[1] = *(const uint4*)(Kp + 8);
            vreg[0] = *(const uint4*)(Vp);
            vreg[1] = *(const uint4*)(Vp + 8);
        }
        __syncthreads();
        *(uint4*)&Ks[lr * 36 + lc0 * 4]     = kreg[0];
        *(uint4*)&Ks[lr * 36 + lc0 * 4 + 4] = kreg[1];
        *(uint4*)&Vs[lr * 36 + lc0 * 4]     = vreg[0];
        *(uint4*)&Vs[lr * 36 + lc0 * 4 + 4] = vreg[1];
        __syncthreads();

        // ---- S = Q K^T  (log2 domain); K fragments via ldmatrix ----
        float sc[8][4];
#pragma unroll
        for (int nt = 0; nt < 8; nt++)
#pragma unroll
            for (int r = 0; r < 4; r++) sc[nt][r] = 0.0f;

#pragma unroll
        for (int kk = 0; kk < 4; kk++) {
            const uint32_t kb = (uint32_t)(kk * 32);
#pragma unroll
            for (int np = 0; np < 4; np++) {
                uint32_t b0, b1, b2, b3;
                ldsm_x4(b0, b1, b2, b3,
                        kbase + kRow + (uint32_t)(np * 16 * 144) + kb);
                uint32_t bA[2] = { b0, b1 };
                uint32_t bB[2] = { b2, b3 };
                mma16(sc[np * 2 + 0], qfr[kk], bA);
                mma16(sc[np * 2 + 1], qfr[kk], bB);
            }
        }

        // ---- causal mask (last two tiles only) ----
        if (tt >= 2 * qt) {
#pragma unroll
            for (int nt = 0; nt < 8; nt++) {
                int col = tt * 64 + nt * 8 + tq * 2;
                if (col > rowsBase)         sc[nt][0] = -1e30f;
                if (col + 1 > rowsBase)     sc[nt][1] = -1e30f;
                if (col > rowsBase + 8)     sc[nt][2] = -1e30f;
                if (col + 1 > rowsBase + 8) sc[nt][3] = -1e30f;
            }
        }

        // ---- online softmax (exp2; rows g, g+8; reduce over 4 lanes) ----
        float mx0 = -1e30f, mx1 = -1e30f;
#pragma unroll
        for (int nt = 0; nt < 8; nt++) {
            mx0 = fmaxf(mx0, fmaxf(sc[nt][0], sc[nt][1]));
            mx1 = fmaxf(mx1, fmaxf(sc[nt][2], sc[nt][3]));
        }
#pragma unroll
        for (int off = 1; off <= 2; off <<= 1) {
            mx0 = fmaxf(mx0, __shfl_xor_sync(0xffffffffu, mx0, off));
            mx1 = fmaxf(mx1, __shfl_xor_sync(0xffffffffu, mx1, off));
        }
        float mn0 = fmaxf(m0, mx0), mn1 = fmaxf(m1, mx1);
        float a0 = exp2f(m0 - mn0), a1 = exp2f(m1 - mn1);
        float rs0 = 0.0f, rs1 = 0.0f;
        uint32_t ph[8][2];   // P in PV A-fragment layout
#pragma unroll
        for (int nt = 0; nt < 8; nt++) {
            float p0 = exp2f(sc[nt][0] - mn0);
            float p1 = exp2f(sc[nt][1] - mn0);
            float p2 = exp2f(sc[nt][2] - mn1);
            float p3 = exp2f(sc[nt][3] - mn1);
            rs0 += p0 + p1;
            rs1 += p2 + p3;
            ph[nt][0] = h2u(__floats2half2_rn(p0, p1));
            ph[nt][1] = h2u(__floats2half2_rn(p2, p3));
        }
#pragma unroll
        for (int off = 1; off <= 2; off <<= 1) {
            rs0 += __shfl_xor_sync(0xffffffffu, rs0, off);
            rs1 += __shfl_xor_sync(0xffffffffu, rs1, off);
        }
        l0 = l0 * a0 + rs0;  m0 = mn0;
        l1 = l1 * a1 + rs1;  m1 = mn1;
#pragma unroll
        for (int dt = 0; dt < 8; dt++) {
            oacc[dt][0] *= a0;  oacc[dt][1] *= a0;
            oacc[dt][2] *= a1;  oacc[dt][3] *= a1;
        }

        // ---- O += P V  (P from regs; V via ldmatrix.x4.trans) ----
#pragma unroll
        for (int kk = 0; kk < 4; kk++) {
            uint32_t pf[4] = { ph[2 * kk][0], ph[2 * kk][1],
                               ph[2 * kk + 1][0], ph[2 * kk + 1][1] };
#pragma unroll
            for (int dt2 = 0; dt2 < 4; dt2++) {
                uint32_t addr = vbase + vRow +
                                (uint32_t)(kk * 16 * 144 + dt2 * 32);
                uint32_t v0, v1, v2, v3;
                ldsm_x4_trans(v0, v1, v2, v3, addr);
                uint32_t bA[2] = { v0, v1 };
                uint32_t bB[2] = { v2, v3 };
                mma16(oacc[dt2 * 2 + 0], pf, bA);
                mma16(oacc[dt2 * 2 + 1], pf, bB);
            }
        }
    }

    // ---- epilogue: normalize, store half to g_ATh ----
    float inv0 = 1.0f / l0, inv1 = 1.0f / l1;
    __half* Og = g_ATh + (size_t)(b * S + qt * 128 + w * 16 + g) * D + h * DK;
#pragma unroll
    for (int dt = 0; dt < 8; dt++) {
        int cc = dt * 8 + tq * 2;
        *(uint32_t*)(Og + cc) =
            h2u(__floats2half2_rn(oacc[dt][0] * inv0, oacc[dt][1] * inv0));
        *(uint32_t*)(Og + 8 * (size_t)D + cc) =
            h2u(__floats2half2_rn(oacc[dt][2] * inv1, oacc[dt][3] * inv1));
    }
}

// ---------------------------------------------------------------------------
extern "C" void kernel_launch(void* const* d_in, const int* in_sizes, int n_in,
                              void* d_out, int out_size)
{
    const float* x   = (const float*)d_in[0];
    const int*   pos = (const int*)  d_in[1];
    const float* WQ  = (const float*)d_in[2];
    const float* WK  = (const float*)d_in[3];
    const float* WV  = (const float*)d_in[4];
    const float* WO  = (const float*)d_in[5];
    float* out = (float*)d_out;

    __half* xh;
    cudaGetSymbolAddress((void**)&xh, g_xh);

    tohalf_kernel<<<(M * D / 4 + 255) / 256, 256>>>(x, xh, M * D / 4);
    tohalfW_kernel<<<dim3(D * D / 4 / 256, 4, 1), 256>>>(WQ, WK, WV, WO);

    cudaFuncSetAttribute(qkv_kernel,
                         cudaFuncAttributeMaxDynamicSharedMemorySize,
                         GEMM_SMEM_BYTES);
    cudaFuncSetAttribute(oproj_kernel,
                         cudaFuncAttributeMaxDynamicSharedMemorySize,
                         GEMM_SMEM_BYTES);
    cudaFuncSetAttribute(attn_kernel,
                         cudaFuncAttributeMaxDynamicSharedMemorySize,
                         ATT_SMEM_BYTES);

    qkv_kernel<<<dim3(D / 128, M / 128, 3), 256, GEMM_SMEM_BYTES>>>(pos);
    attn_kernel<<<dim3(S / 128, NH, B), 256, ATT_SMEM_BYTES>>>();
    oproj_kernel<<<dim3(D / 128, M / 128, 1), 256, GEMM_SMEM_BYTES>>>(out);
}